// round 2
// baseline (speedup 1.0000x reference)
#include <cuda_runtime.h>
#include <math.h>

#define G   8      // batch rows per CTA
#define NT  256    // threads per CTA (8 warps = 8 heads)

// smem float counts
#define RT_OFF   0                       // [256][8]  R transposed
#define QS_OFF   (RT_OFF + 2048)         // [8][256]  Q
#define PY_OFF   (QS_OFF + 2048)         // [8][8][384] P then Y
#define XS_OFF   (PY_OFF + 24576)        // [32][384] X tile (one g at a time)
#define OV_OFF   (XS_OFF + 12288)        // [256][8]  attn output transposed
#define AT_OFF   (OV_OFF + 2048)         // [8][32]   scores
#define WT_OFF   (AT_OFF + 256)          // [8][32]   softmax weights
#define R1_OFF   (WT_OFF + 256)          // [8][8]    reductions
#define R2_OFF   (R1_OFF + 64)
#define MU_OFF   (R2_OFF + 64)           // [8]
#define RS_OFF   (MU_OFF + 8)            // [8]
#define IN_OFF   (RS_OFF + 8)            // ints: list[32], m, allmask
#define SMEM_FLOATS (IN_OFF)
#define SMEM_BYTES  (SMEM_FLOATS * 4 + 34 * 4)

__device__ __forceinline__ float wsum(float v) {
#pragma unroll
    for (int o = 16; o > 0; o >>= 1) v += __shfl_xor_sync(0xffffffffu, v, o);
    return v;
}
__device__ __forceinline__ float wmax(float v) {
#pragma unroll
    for (int o = 16; o > 0; o >>= 1) v = fmaxf(v, __shfl_xor_sync(0xffffffffu, v, o));
    return v;
}

__global__ __launch_bounds__(NT, 1)
void ta_kernel(const float* __restrict__ node,
               const float* __restrict__ timef,
               const float* __restrict__ edge,
               const float* __restrict__ nnode,
               const float* __restrict__ ntime,
               const int* __restrict__ mask,
               const float* __restrict__ WQ,
               const float* __restrict__ WKV,
               const float* __restrict__ WO,
               const float* __restrict__ bO,
               const float* __restrict__ gamma,
               const float* __restrict__ beta,
               float* __restrict__ out,
               int B)
{
    extern __shared__ float smf[];
    float* RT  = smf + RT_OFF;
    float* Qs  = smf + QS_OFF;
    float* PY  = smf + PY_OFF;
    float* Xs  = smf + XS_OFF;
    float* OvT = smf + OV_OFF;
    float* Att = smf + AT_OFF;
    float* Wt  = smf + WT_OFF;
    float* red1 = smf + R1_OFF;
    float* red2 = smf + R2_OFF;
    float* muS = smf + MU_OFF;
    float* rsS = smf + RS_OFF;
    int*   lst = (int*)(smf + IN_OFF);   // [32]
    int*   mS  = lst + 32;               // [0]=m, [1]=allmask

    const int t = threadIdx.x;
    const int wid = t >> 5, lane = t & 31;
    const int b0 = blockIdx.x * G;

    // ---- Phase 0: load R = concat(node, time), transposed [j][g] ----
    for (int idx = t; idx < G * 256; idx += NT) {
        int g = idx >> 8, j = idx & 255;
        int bb = b0 + g; if (bb > B - 1) bb = B - 1;
        long long b = bb;
        float v = (j < 128) ? node[b * 128 + j] : timef[b * 128 + (j - 128)];
        RT[j * G + g] = v;
    }
    __syncthreads();

    // ---- Phase 1: Q[g][o] = sum_i R[g][i] * WQ[i*256+o]  (o = t) ----
    {
        float acc[G];
#pragma unroll
        for (int g = 0; g < G; ++g) acc[g] = 0.f;
#pragma unroll 4
        for (int i = 0; i < 256; ++i) {
            float wq = __ldg(&WQ[i * 256 + t]);
            float4 r0 = *(const float4*)&RT[i * G];
            float4 r1 = *(const float4*)&RT[i * G + 4];
            acc[0] = fmaf(r0.x, wq, acc[0]);
            acc[1] = fmaf(r0.y, wq, acc[1]);
            acc[2] = fmaf(r0.z, wq, acc[2]);
            acc[3] = fmaf(r0.w, wq, acc[3]);
            acc[4] = fmaf(r1.x, wq, acc[4]);
            acc[5] = fmaf(r1.y, wq, acc[5]);
            acc[6] = fmaf(r1.z, wq, acc[6]);
            acc[7] = fmaf(r1.w, wq, acc[7]);
        }
#pragma unroll
        for (int g = 0; g < G; ++g) Qs[g * 256 + t] = acc[g];
    }
    __syncthreads();

    // ---- Phase 2: P[g][h][i] = sum_d WKV[i*512 + h*32 + d] * Q[g][h*32+d] ----
#pragma unroll 1
    for (int k = 0; k < 12; ++k) {
        int flat = k * NT + t;           // 0..3071
        int h = flat / 384;
        int i = flat - h * 384;
        const float4* wk4 = (const float4*)(WKV + (size_t)i * 512 + h * 32);
        float acc[G];
#pragma unroll
        for (int g = 0; g < G; ++g) acc[g] = 0.f;
#pragma unroll
        for (int d4 = 0; d4 < 8; ++d4) {
            float4 w = __ldg(&wk4[d4]);
#pragma unroll
            for (int g = 0; g < G; ++g) {
                float4 q = *(const float4*)&Qs[g * 256 + h * 32 + d4 * 4];
                acc[g] = fmaf(w.x, q.x, fmaf(w.y, q.y, fmaf(w.z, q.z, fmaf(w.w, q.w, acc[g]))));
            }
        }
#pragma unroll
        for (int g = 0; g < G; ++g) PY[(g * 8 + h) * 384 + i] = acc[g];
    }
    __syncthreads();

    // ---- Phase 3: per batch row: mask -> X load -> scores -> softmax -> Y ----
    for (int g = 0; g < G; ++g) {
        int bb = b0 + g; if (bb > B - 1) bb = B - 1;
        long long b = bb;

        if (wid == 0) {
            int mk = mask[b * 32 + lane];
            unsigned bal = __ballot_sync(0xffffffffu, mk != 0);
            int m = __popc(bal);
            if (m == 0) {
                lst[lane] = lane;                               // all-masked: uniform over all 32
            } else if (mk != 0) {
                lst[__popc(bal & ((1u << lane) - 1u))] = lane;  // compact unmasked indices
            }
            if (lane == 0) { mS[0] = (m == 0) ? 32 : m; mS[1] = (m == 0); }
        }
        __syncthreads();
        const int m = mS[0];
        const int allm = mS[1];

        // load X rows (concat order: nbr_node | edge | nbr_time), float4
        {
            const float4* nn4 = (const float4*)nnode;
            const float4* ed4 = (const float4*)edge;
            const float4* et4 = (const float4*)ntime;
            int total = m * 96;
            for (int idx = t; idx < total; idx += NT) {
                int s = idx / 96, c4 = idx - s * 96;
                long long rb = (b * 32 + lst[s]) * 32;   // float4 units
                float4 v;
                if (c4 < 32)      v = __ldg(&nn4[rb + c4]);
                else if (c4 < 64) v = __ldg(&ed4[rb + (c4 - 32)]);
                else              v = __ldg(&et4[rb + (c4 - 64)]);
                *(float4*)&Xs[s * 384 + c4 * 4] = v;
            }
        }
        __syncthreads();

        // scores + softmax: warp `wid` owns head h = wid
        {
            const float* prow = &PY[(g * 8 + wid) * 384];
            for (int s = 0; s < m; ++s) {
                const float* xrow = &Xs[s * 384];
                float p = 0.f;
#pragma unroll
                for (int k = 0; k < 12; ++k)
                    p = fmaf(xrow[lane + 32 * k], prow[lane + 32 * k], p);
                p = wsum(p);
                if (lane == 0)
                    Att[wid * 32 + s] = allm ? 0.f : p * 0.17677669529663687f;
            }
            __syncwarp();
            float v = (lane < m) ? Att[wid * 32 + lane] : -3.0e38f;
            float mx = wmax(v);
            float e = (lane < m) ? expf(v - mx) : 0.f;
            float ss = wsum(e);
            Wt[wid * 32 + lane] = e / ss;
        }
        __syncthreads();

        // Y[g][h][i] = sum_s w[h][s] * X[s][i]   (overwrites P[g] — dead now)
#pragma unroll 1
        for (int k = 0; k < 12; ++k) {
            int flat = k * NT + t;
            int h = flat / 384;
            int i = flat - h * 384;
            float acc = 0.f;
            for (int s = 0; s < m; ++s)
                acc = fmaf(Wt[h * 32 + s], Xs[s * 384 + i], acc);
            PY[(g * 8 + h) * 384 + i] = acc;
        }
        __syncthreads();
    }

    // ---- Phase 4: attn out O[g][o] = sum_i Y[g][h][i] * WKV[i*512 + 256 + o], o=t, h=o>>5 ----
    {
        const int h = t >> 5;
        float acc[G];
#pragma unroll
        for (int g = 0; g < G; ++g) acc[g] = 0.f;
        const float* wvp = WKV + 256 + t;
#pragma unroll 4
        for (int i = 0; i < 384; ++i) {
            float wv = __ldg(&wvp[(size_t)i * 512]);
#pragma unroll
            for (int g = 0; g < G; ++g)
                acc[g] = fmaf(PY[(g * 8 + h) * 384 + i], wv, acc[g]);
        }
#pragma unroll
        for (int g = 0; g < G; ++g) OvT[t * G + g] = acc[g];
    }
    __syncthreads();

    // ---- Phase 5: out = O @ WO + bO + R, then LayerNorm ----
    {
        float acc[G];
#pragma unroll
        for (int g = 0; g < G; ++g) acc[g] = 0.f;
#pragma unroll 4
        for (int i = 0; i < 256; ++i) {
            float wo = __ldg(&WO[i * 256 + t]);
            float4 o0 = *(const float4*)&OvT[i * G];
            float4 o1 = *(const float4*)&OvT[i * G + 4];
            acc[0] = fmaf(o0.x, wo, acc[0]);
            acc[1] = fmaf(o0.y, wo, acc[1]);
            acc[2] = fmaf(o0.z, wo, acc[2]);
            acc[3] = fmaf(o0.w, wo, acc[3]);
            acc[4] = fmaf(o1.x, wo, acc[4]);
            acc[5] = fmaf(o1.y, wo, acc[5]);
            acc[6] = fmaf(o1.z, wo, acc[6]);
            acc[7] = fmaf(o1.w, wo, acc[7]);
        }
        float bo = __ldg(&bO[t]);
        float4 rr0 = *(const float4*)&RT[t * G];
        float4 rr1 = *(const float4*)&RT[t * G + 4];
        float xg[G];
        xg[0] = acc[0] + bo + rr0.x;
        xg[1] = acc[1] + bo + rr0.y;
        xg[2] = acc[2] + bo + rr0.z;
        xg[3] = acc[3] + bo + rr0.w;
        xg[4] = acc[4] + bo + rr1.x;
        xg[5] = acc[5] + bo + rr1.y;
        xg[6] = acc[6] + bo + rr1.z;
        xg[7] = acc[7] + bo + rr1.w;

#pragma unroll
        for (int g = 0; g < G; ++g) {
            float s1 = wsum(xg[g]);
            float s2 = wsum(xg[g] * xg[g]);
            if (lane == 0) { red1[wid * 8 + g] = s1; red2[wid * 8 + g] = s2; }
        }
        __syncthreads();
        if (t < 8) {
            float t1 = 0.f, t2 = 0.f;
#pragma unroll
            for (int w = 0; w < 8; ++w) { t1 += red1[w * 8 + t]; t2 += red2[w * 8 + t]; }
            float mu = t1 * (1.0f / 256.0f);
            float var = t2 * (1.0f / 256.0f) - mu * mu;
            muS[t] = mu;
            rsS[t] = rsqrtf(var + 1e-5f);
        }
        __syncthreads();
        float gm = __ldg(&gamma[t]), bt = __ldg(&beta[t]);
#pragma unroll
        for (int g = 0; g < G; ++g) {
            int b = b0 + g;
            if (b < B)
                out[(size_t)b * 256 + t] = (xg[g] - muS[g]) * rsS[g] * gm + bt;
        }
    }
}

extern "C" void kernel_launch(void* const* d_in, const int* in_sizes, int n_in,
                              void* d_out, int out_size) {
    (void)n_in; (void)out_size;
    const float* node  = (const float*)d_in[0];
    const float* timef = (const float*)d_in[1];
    const float* edge  = (const float*)d_in[2];
    const float* nnode = (const float*)d_in[3];
    const float* ntime = (const float*)d_in[4];
    const int*   mask  = (const int*)d_in[5];
    const float* WQ    = (const float*)d_in[6];
    const float* WKV   = (const float*)d_in[7];
    const float* WO    = (const float*)d_in[8];
    const float* bO    = (const float*)d_in[9];
    const float* gamma = (const float*)d_in[10];
    const float* beta  = (const float*)d_in[11];
    float* out = (float*)d_out;

    int B = in_sizes[0] / 128;
    int blocks = (B + G - 1) / G;

    cudaFuncSetAttribute(ta_kernel, cudaFuncAttributeMaxDynamicSharedMemorySize, SMEM_BYTES);
    ta_kernel<<<blocks, NT, SMEM_BYTES>>>(node, timef, edge, nnode, ntime, mask,
                                          WQ, WKV, WO, bO, gamma, beta, out, B);
}

// round 3
// speedup vs baseline: 1.4140x; 1.4140x over previous
#include <cuda_runtime.h>
#include <math.h>

#define G    8
#define NT   512
#define XSTR 388    // padded X row stride (floats)
#define PSTR 388    // padded P/Y row stride (floats)

#define RT_OFF   0                        // [256][8]
#define QS_OFF   2048                     // [8][256], reused as OvT [256][8]
#define PY_OFF   4096                     // [8g][8h][388]
#define XS_OFF   (PY_OFF + 24832)         // 2 x [32][388]
#define AT_OFF   (XS_OFF + 24832)         // [32][9]
#define WT_OFF   (AT_OFF + 288)           // [8][32]
#define RD1_OFF  (WT_OFF + 256)           // [16][4]
#define RD2_OFF  (RD1_OFF + 64)
#define MU_OFF   (RD2_OFF + 64)           // [8]
#define RS_OFF   (MU_OFF + 8)             // [8]
#define CODE_OFF (RS_OFF + 8)             // [8][32] ints
#define SMEM_FLOATS (CODE_OFF + 256)
#define SMEM_BYTES  (SMEM_FLOATS * 4)

__device__ __forceinline__ float wsum(float v) {
#pragma unroll
    for (int o = 16; o > 0; o >>= 1) v += __shfl_xor_sync(0xffffffffu, v, o);
    return v;
}
__device__ __forceinline__ float wmax(float v) {
#pragma unroll
    for (int o = 16; o > 0; o >>= 1) v = fmaxf(v, __shfl_xor_sync(0xffffffffu, v, o));
    return v;
}
__device__ __forceinline__ void cpasync16(void* dst, const void* src) {
    unsigned d = (unsigned)__cvta_generic_to_shared(dst);
    asm volatile("cp.async.cg.shared.global [%0], [%1], 16;\n" :: "r"(d), "l"(src));
}
__device__ __forceinline__ void cpcommit() {
    asm volatile("cp.async.commit_group;\n" ::: "memory");
}
__device__ __forceinline__ void cpwaitall() {
    asm volatile("cp.async.wait_group 0;\n" ::: "memory");
}

// load 32 rows x 384 floats (3072 float4) of concat(nbr_node|edge|nbr_time) for batch row b
__device__ __forceinline__ void prefetchX(float* Xbuf, long long b,
                                          const float4* nn4, const float4* ed4, const float4* et4,
                                          int start, int stride) {
    for (int idx = start; idx < 3072; idx += stride) {
        int s = idx / 96, c4 = idx - s * 96;
        long long rb = (b * 32 + s) * 32;
        const float4* src = (c4 < 32) ? nn4 + rb + c4
                          : (c4 < 64) ? ed4 + rb + (c4 - 32)
                                      : et4 + rb + (c4 - 64);
        cpasync16(&Xbuf[s * XSTR + c4 * 4], src);
    }
}

__global__ __launch_bounds__(NT, 1)
void ta_kernel(const float* __restrict__ node,
               const float* __restrict__ timef,
               const float* __restrict__ edge,
               const float* __restrict__ nnode,
               const float* __restrict__ ntime,
               const int* __restrict__ mask,
               const float* __restrict__ WQ,
               const float* __restrict__ WKV,
               const float* __restrict__ WO,
               const float* __restrict__ bO,
               const float* __restrict__ gamma,
               const float* __restrict__ beta,
               float* __restrict__ out,
               int B)
{
    extern __shared__ float smf[];
    float* RT   = smf + RT_OFF;
    float* Qs   = smf + QS_OFF;      // Q, later OvT
    float* PY   = smf + PY_OFF;      // P then Y (per-g blocks)
    float* XS   = smf + XS_OFF;
    float* Att  = smf + AT_OFF;
    float* Wt   = smf + WT_OFF;
    float* red1 = smf + RD1_OFF;
    float* red2 = smf + RD2_OFF;
    float* muS  = smf + MU_OFF;
    float* rsS  = smf + RS_OFF;
    int*   codeS = (int*)(smf + CODE_OFF);

    const int t = threadIdx.x;
    const int wid = t >> 5, lane = t & 31;
    const int b0 = blockIdx.x * G;

    const float4* nn4 = (const float4*)nnode;
    const float4* ed4 = (const float4*)edge;
    const float4* et4 = (const float4*)ntime;

    // ---- prefetch X[g=0] (overlaps with phases 0-2) ----
    {
        int bb = b0; if (bb > B - 1) bb = B - 1;
        prefetchX(XS, (long long)bb, nn4, ed4, et4, t, NT);
        cpcommit();
    }

    // ---- phase 0: RT (R transposed) + mask codes ----
    for (int idx = t; idx < G * 256; idx += NT) {
        int g = idx & 7, j = idx >> 3;
        int bb = b0 + g; if (bb > B - 1) bb = B - 1;
        long long b = bb;
        float v = (j < 128) ? node[b * 128 + j] : timef[b * 128 + (j - 128)];
        RT[j * G + g] = v;
    }
    if (t < 256) {
        int g = wid;                 // warp g handles batch-row g's mask
        int bb = b0 + g; if (bb > B - 1) bb = B - 1;
        int mk = mask[(long long)bb * 32 + lane];
        unsigned bal = __ballot_sync(0xffffffffu, mk != 0);
        codeS[g * 32 + lane] = (bal == 0u) ? 2 : (mk ? 0 : 1);
    }
    __syncthreads();

    // ---- phase 1: Q[g][o] = R[g] . WQ[:,o];  o = t&255, 4 g per half ----
    {
        const int o = t & 255, gh = t >> 8;
        float a0 = 0.f, a1 = 0.f, a2 = 0.f, a3 = 0.f;
#pragma unroll 4
        for (int i = 0; i < 256; ++i) {
            float wq = __ldg(&WQ[i * 256 + o]);
            float4 r = *(const float4*)&RT[i * G + gh * 4];
            a0 = fmaf(r.x, wq, a0);
            a1 = fmaf(r.y, wq, a1);
            a2 = fmaf(r.z, wq, a2);
            a3 = fmaf(r.w, wq, a3);
        }
        Qs[(gh * 4 + 0) * 256 + o] = a0;
        Qs[(gh * 4 + 1) * 256 + o] = a1;
        Qs[(gh * 4 + 2) * 256 + o] = a2;
        Qs[(gh * 4 + 3) * 256 + o] = a3;
    }
    __syncthreads();

    // ---- phase 2: P[g][h][i] = sum_d WKV[i, h*32+d] * Q[g, h*32+d] ----
#pragma unroll 1
    for (int k = 0; k < 6; ++k) {
        int flat = k * NT + t;            // 0..3071 over (h,i)
        int h = flat / 384;
        int i = flat - h * 384;
        const float4* wk4 = (const float4*)(WKV + (size_t)i * 512 + h * 32);
        float acc[8];
#pragma unroll
        for (int g = 0; g < 8; ++g) acc[g] = 0.f;
#pragma unroll
        for (int d4 = 0; d4 < 8; ++d4) {
            float4 w = __ldg(&wk4[d4]);
#pragma unroll
            for (int g = 0; g < 8; ++g) {
                float4 q = *(const float4*)&Qs[g * 256 + h * 32 + d4 * 4];
                acc[g] = fmaf(w.x, q.x, fmaf(w.y, q.y, fmaf(w.z, q.z, fmaf(w.w, q.w, acc[g]))));
            }
        }
#pragma unroll
        for (int g = 0; g < 8; ++g) PY[(g * 8 + h) * PSTR + i] = acc[g];
    }
    cpwaitall();          // X[0] resident
    __syncthreads();

    // ---- phase 3: per-g attention, double-buffered X ----
#pragma unroll 1
    for (int g = 0; g < G; ++g) {
        float* Xbuf = XS + (g & 1) * (32 * XSTR);

        if (t < 256) {
            // scores: thread -> (s,h)
            const int s = t >> 3, h = t & 7;
            int cde = codeS[g * 32 + s];
            float sc;
            if (cde == 0) {
                const float4* Xrow = (const float4*)&Xbuf[s * XSTR];
                const float4* Prow = (const float4*)&PY[(g * 8 + h) * PSTR];
                float a0 = 0.f, a1 = 0.f, a2 = 0.f, a3 = 0.f;
#pragma unroll 4
                for (int c4 = 0; c4 < 96; c4 += 4) {
                    float4 x0 = Xrow[c4 + 0], p0 = Prow[c4 + 0];
                    float4 x1 = Xrow[c4 + 1], p1 = Prow[c4 + 1];
                    float4 x2 = Xrow[c4 + 2], p2 = Prow[c4 + 2];
                    float4 x3 = Xrow[c4 + 3], p3 = Prow[c4 + 3];
                    a0 = fmaf(x0.x, p0.x, fmaf(x0.y, p0.y, fmaf(x0.z, p0.z, fmaf(x0.w, p0.w, a0))));
                    a1 = fmaf(x1.x, p1.x, fmaf(x1.y, p1.y, fmaf(x1.z, p1.z, fmaf(x1.w, p1.w, a1))));
                    a2 = fmaf(x2.x, p2.x, fmaf(x2.y, p2.y, fmaf(x2.z, p2.z, fmaf(x2.w, p2.w, a2))));
                    a3 = fmaf(x3.x, p3.x, fmaf(x3.y, p3.y, fmaf(x3.z, p3.z, fmaf(x3.w, p3.w, a3))));
                }
                sc = ((a0 + a1) + (a2 + a3)) * 0.17677669529663687f;
            } else {
                sc = (cde == 1) ? -1e10f : 0.f;
            }
            Att[s * 9 + h] = sc;

            asm volatile("bar.sync 1, 256;" ::: "memory");

            // softmax: warp wid owns head h=wid, lane = s
            float v = Att[lane * 9 + wid];
            float mx = wmax(v);
            float e = __expf(v - mx);
            float ss = wsum(e);
            Wt[wid * 32 + lane] = e / ss;
        } else {
            // prefetch X[g+1] into other buffer
            if (g < G - 1) {
                int bb = b0 + g + 1; if (bb > B - 1) bb = B - 1;
                prefetchX(XS + ((g + 1) & 1) * (32 * XSTR), (long long)bb,
                          nn4, ed4, et4, t - 256, 256);
            }
            cpcommit();
        }
        __syncthreads();   // Wt ready

        // Y[g][h][i] = sum_s w[h,s] * X[s][i]; thread: h = t>>6, cols col+64j
        {
            const int h = t >> 6, col = t & 63;
            const float* Wrow = &Wt[h * 32];
            float a0 = 0.f, a1 = 0.f, a2 = 0.f, a3 = 0.f, a4 = 0.f, a5 = 0.f;
#pragma unroll 1
            for (int s = 0; s < 32; ++s) {
                float w = Wrow[s];
                if (w != 0.f) {
                    const float* xr = &Xbuf[s * XSTR + col];
                    a0 = fmaf(w, xr[0],   a0);
                    a1 = fmaf(w, xr[64],  a1);
                    a2 = fmaf(w, xr[128], a2);
                    a3 = fmaf(w, xr[192], a3);
                    a4 = fmaf(w, xr[256], a4);
                    a5 = fmaf(w, xr[320], a5);
                }
            }
            float* yr = &PY[(g * 8 + h) * PSTR + col];   // overwrite P[g] (dead)
            yr[0] = a0; yr[64] = a1; yr[128] = a2;
            yr[192] = a3; yr[256] = a4; yr[320] = a5;
        }
        cpwaitall();
        __syncthreads();   // Y[g] ready; buffers safe to swap
    }

    // ---- phase 4: O[g][o] = sum_i Y[g][h(o)][i] * WV[i][o] ----
    {
        const int o = t & 255, gh = t >> 8, h = o >> 5;
        float acc[4];
#pragma unroll
        for (int gi = 0; gi < 4; ++gi) acc[gi] = 0.f;
        const float* wvp = WKV + 256 + o;
#pragma unroll 2
        for (int i4 = 0; i4 < 96; ++i4) {
            float w0 = __ldg(&wvp[(size_t)(i4 * 4 + 0) * 512]);
            float w1 = __ldg(&wvp[(size_t)(i4 * 4 + 1) * 512]);
            float w2 = __ldg(&wvp[(size_t)(i4 * 4 + 2) * 512]);
            float w3 = __ldg(&wvp[(size_t)(i4 * 4 + 3) * 512]);
#pragma unroll
            for (int gi = 0; gi < 4; ++gi) {
                float4 y = *(const float4*)&PY[((gh * 4 + gi) * 8 + h) * PSTR + i4 * 4];
                acc[gi] = fmaf(y.x, w0, fmaf(y.y, w1, fmaf(y.z, w2, fmaf(y.w, w3, acc[gi]))));
            }
        }
        __syncthreads();   // Qs (alias OvT) fully dead
        *(float4*)&Qs[o * 8 + gh * 4] = make_float4(acc[0], acc[1], acc[2], acc[3]);
    }
    __syncthreads();

    // ---- phase 5: out = O @ WO + bO + R, LayerNorm ----
    {
        const int o = t & 255, gh = t >> 8;
        const float* OvT = Qs;
        float a0 = 0.f, a1 = 0.f, a2 = 0.f, a3 = 0.f;
#pragma unroll 4
        for (int i = 0; i < 256; ++i) {
            float wo = __ldg(&WO[i * 256 + o]);
            float4 ov = *(const float4*)&OvT[i * 8 + gh * 4];
            a0 = fmaf(ov.x, wo, a0);
            a1 = fmaf(ov.y, wo, a1);
            a2 = fmaf(ov.z, wo, a2);
            a3 = fmaf(ov.w, wo, a3);
        }
        float bo = __ldg(&bO[o]);
        float4 rr = *(const float4*)&RT[o * 8 + gh * 4];
        float xg[4];
        xg[0] = a0 + bo + rr.x;
        xg[1] = a1 + bo + rr.y;
        xg[2] = a2 + bo + rr.z;
        xg[3] = a3 + bo + rr.w;

#pragma unroll
        for (int gi = 0; gi < 4; ++gi) {
            float s1 = wsum(xg[gi]);
            float s2 = wsum(xg[gi] * xg[gi]);
            if (lane == 0) { red1[wid * 4 + gi] = s1; red2[wid * 4 + gi] = s2; }
        }
        __syncthreads();
        if (t < 8) {
            int g = t, wbase = (g < 4) ? 0 : 8, gi = g & 3;
            float t1 = 0.f, t2 = 0.f;
#pragma unroll
            for (int w = 0; w < 8; ++w) {
                t1 += red1[(wbase + w) * 4 + gi];
                t2 += red2[(wbase + w) * 4 + gi];
            }
            float mu = t1 * (1.0f / 256.0f);
            float var = t2 * (1.0f / 256.0f) - mu * mu;
            muS[g] = mu;
            rsS[g] = rsqrtf(var + 1e-5f);
        }
        __syncthreads();
        float gm = __ldg(&gamma[o]), bt = __ldg(&beta[o]);
#pragma unroll
        for (int gi = 0; gi < 4; ++gi) {
            int g = gh * 4 + gi;
            int b = b0 + g;
            if (b < B)
                out[(size_t)b * 256 + o] = (xg[gi] - muS[g]) * rsS[g] * gm + bt;
        }
    }
}

extern "C" void kernel_launch(void* const* d_in, const int* in_sizes, int n_in,
                              void* d_out, int out_size) {
    (void)n_in; (void)out_size;
    const float* node  = (const float*)d_in[0];
    const float* timef = (const float*)d_in[1];
    const float* edge  = (const float*)d_in[2];
    const float* nnode = (const float*)d_in[3];
    const float* ntime = (const float*)d_in[4];
    const int*   mask  = (const int*)d_in[5];
    const float* WQ    = (const float*)d_in[6];
    const float* WKV   = (const float*)d_in[7];
    const float* WO    = (const float*)d_in[8];
    const float* bO    = (const float*)d_in[9];
    const float* gamma = (const float*)d_in[10];
    const float* beta  = (const float*)d_in[11];
    float* out = (float*)d_out;

    int B = in_sizes[0] / 128;
    int blocks = (B + G - 1) / G;

    cudaFuncSetAttribute(ta_kernel, cudaFuncAttributeMaxDynamicSharedMemorySize, SMEM_BYTES);
    ta_kernel<<<blocks, NT, SMEM_BYTES>>>(node, timef, edge, nnode, ntime, mask,
                                          WQ, WKV, WO, bO, gamma, beta, out, B);
}

// round 4
// speedup vs baseline: 1.4900x; 1.0537x over previous
#include <cuda_runtime.h>
#include <math.h>

#define G    8
#define NT   1024
#define XSTR 388
#define PSTR 388

#define RT_OFF   0                        // [256][8]
#define QS_OFF   2048                     // [8][256] Q, later OvT [256][8]
#define PY_OFF   4096                     // [8g][8h][388]
#define XS_OFF   (PY_OFF + 24832)         // 2 x [32][388]
#define XS1_OFF  (XS_OFF + 12416)
#define AT_OFF   (XS_OFF + 24832)         // [32][9]
#define WT_OFF   (AT_OFF + 288)           // [8][32]
#define RD1_OFF  (WT_OFF + 256)           // [32][2]
#define RD2_OFF  (RD1_OFF + 64)           // [32][2]
#define MU_OFF   (RD2_OFF + 64)           // [8]
#define RS_OFF   (MU_OFF + 8)             // [8]
#define CODE_OFF (RS_OFF + 8)             // [8][32] ints
#define SMEM_FLOATS (CODE_OFF + 256)
#define SMEM_BYTES  (SMEM_FLOATS * 4)

__device__ __forceinline__ float wsum(float v) {
#pragma unroll
    for (int o = 16; o > 0; o >>= 1) v += __shfl_xor_sync(0xffffffffu, v, o);
    return v;
}
__device__ __forceinline__ float wmax(float v) {
#pragma unroll
    for (int o = 16; o > 0; o >>= 1) v = fmaxf(v, __shfl_xor_sync(0xffffffffu, v, o));
    return v;
}
__device__ __forceinline__ void cpasync16(void* dst, const void* src) {
    unsigned d = (unsigned)__cvta_generic_to_shared(dst);
    asm volatile("cp.async.cg.shared.global [%0], [%1], 16;\n" :: "r"(d), "l"(src));
}
__device__ __forceinline__ void cpcommit() {
    asm volatile("cp.async.commit_group;\n" ::: "memory");
}
__device__ __forceinline__ void cpwaitall() {
    asm volatile("cp.async.wait_group 0;\n" ::: "memory");
}

__device__ __forceinline__ void prefetchX(float* Xbuf, long long b,
                                          const float4* nn4, const float4* ed4, const float4* et4,
                                          int start, int stride) {
    for (int idx = start; idx < 3072; idx += stride) {
        int s = idx / 96, c4 = idx - s * 96;
        long long rb = (b * 32 + s) * 32;
        const float4* src = (c4 < 32) ? nn4 + rb + c4
                          : (c4 < 64) ? ed4 + rb + (c4 - 32)
                                      : et4 + rb + (c4 - 64);
        cpasync16(&Xbuf[s * XSTR + c4 * 4], src);
    }
}

__global__ __launch_bounds__(NT, 1)
void ta_kernel(const float* __restrict__ node,
               const float* __restrict__ timef,
               const float* __restrict__ edge,
               const float* __restrict__ nnode,
               const float* __restrict__ ntime,
               const int* __restrict__ mask,
               const float* __restrict__ WQ,
               const float* __restrict__ WKV,
               const float* __restrict__ WO,
               const float* __restrict__ bO,
               const float* __restrict__ gamma,
               const float* __restrict__ beta,
               float* __restrict__ out,
               int B)
{
    extern __shared__ float smf[];
    float* RT   = smf + RT_OFF;
    float* Qs   = smf + QS_OFF;
    float* PY   = smf + PY_OFF;
    float* XS   = smf + XS_OFF;
    float* XS1  = smf + XS1_OFF;
    float* Att  = smf + AT_OFF;
    float* Wt   = smf + WT_OFF;
    float* red1 = smf + RD1_OFF;
    float* red2 = smf + RD2_OFF;
    float* muS  = smf + MU_OFF;
    float* rsS  = smf + RS_OFF;
    int*   codeS = (int*)(smf + CODE_OFF);

    const int t = threadIdx.x;
    const int wid = t >> 5, lane = t & 31;
    const int b0 = blockIdx.x * G;

    const float4* nn4 = (const float4*)nnode;
    const float4* ed4 = (const float4*)edge;
    const float4* et4 = (const float4*)ntime;

    // prefetch X[g=0] into buf0 (overlaps phases 0-2)
    {
        int bb = b0; if (bb > B - 1) bb = B - 1;
        prefetchX(XS, (long long)bb, nn4, ed4, et4, t, NT);
        cpcommit();
    }

    // ---- phase 0: RT + mask codes ----
    for (int idx = t; idx < G * 256; idx += NT) {
        int g = idx & 7, j = idx >> 3;
        int bb = b0 + g; if (bb > B - 1) bb = B - 1;
        long long b = bb;
        float v = (j < 128) ? node[b * 128 + j] : timef[b * 128 + (j - 128)];
        RT[j * G + g] = v;
    }
    if (t < 256) {
        int g = wid;
        int bb = b0 + g; if (bb > B - 1) bb = B - 1;
        int mk = mask[(long long)bb * 32 + lane];
        unsigned bal = __ballot_sync(0xffffffffu, mk != 0);
        codeS[g * 32 + lane] = (bal == 0u) ? 2 : (mk ? 0 : 1);
    }
    __syncthreads();

    // ---- phase 1: Q partials over i-quarters, staged in XS1 ----
    {
        const int o = t & 255, q = t >> 8;
        float acc[8];
#pragma unroll
        for (int g = 0; g < 8; ++g) acc[g] = 0.f;
        const int i0 = q * 64;
#pragma unroll 4
        for (int ii = 0; ii < 64; ++ii) {
            int i = i0 + ii;
            float wq = __ldg(&WQ[i * 256 + o]);
            float4 r0 = *(const float4*)&RT[i * 8];
            float4 r1 = *(const float4*)&RT[i * 8 + 4];
            acc[0] = fmaf(r0.x, wq, acc[0]);
            acc[1] = fmaf(r0.y, wq, acc[1]);
            acc[2] = fmaf(r0.z, wq, acc[2]);
            acc[3] = fmaf(r0.w, wq, acc[3]);
            acc[4] = fmaf(r1.x, wq, acc[4]);
            acc[5] = fmaf(r1.y, wq, acc[5]);
            acc[6] = fmaf(r1.z, wq, acc[6]);
            acc[7] = fmaf(r1.w, wq, acc[7]);
        }
        float* stg = XS1 + q * 2048 + o * 8;
        *(float4*)stg       = make_float4(acc[0], acc[1], acc[2], acc[3]);
        *(float4*)(stg + 4) = make_float4(acc[4], acc[5], acc[6], acc[7]);
    }
    __syncthreads();
    {
#pragma unroll
        for (int r = 0; r < 2; ++r) {
            int idx = r * 1024 + t;
            float s = XS1[idx] + XS1[2048 + idx] + XS1[4096 + idx] + XS1[6144 + idx];
            Qs[(idx & 7) * 256 + (idx >> 3)] = s;
        }
    }
    __syncthreads();

    // ---- phase 2: P[g][h][i] ----
#pragma unroll 1
    for (int k = 0; k < 3; ++k) {
        int flat = k * NT + t;            // 0..3071
        int h = flat / 384;
        int i = flat - h * 384;
        const float4* wk4 = (const float4*)(WKV + (size_t)i * 512 + h * 32);
        float acc[8];
#pragma unroll
        for (int g = 0; g < 8; ++g) acc[g] = 0.f;
#pragma unroll
        for (int d4 = 0; d4 < 8; ++d4) {
            float4 w = __ldg(&wk4[d4]);
#pragma unroll
            for (int g = 0; g < 8; ++g) {
                float4 qv = *(const float4*)&Qs[g * 256 + h * 32 + d4 * 4];
                acc[g] = fmaf(w.x, qv.x, fmaf(w.y, qv.y, fmaf(w.z, qv.z, fmaf(w.w, qv.w, acc[g]))));
            }
        }
#pragma unroll
        for (int g = 0; g < 8; ++g) PY[(g * 8 + h) * PSTR + i] = acc[g];
    }
    cpwaitall();
    __syncthreads();

    // ---- phase 3: per-g attention ----
#pragma unroll 1
    for (int g = 0; g < G; ++g) {
        float* Xbuf = XS + (g & 1) * 12416;

        // prefetch X[g+1] into other buffer (async, all threads)
        if (g < G - 1) {
            int bb = b0 + g + 1; if (bb > B - 1) bb = B - 1;
            prefetchX(XS + ((g + 1) & 1) * 12416, (long long)bb, nn4, ed4, et4, t, NT);
        }
        cpcommit();

        // scores: warp = s, lanes = (h, q); i interleaved as 16j + 4q
        {
            const int s = wid;
            const int h = lane >> 2, q = lane & 3;
            int cde = codeS[g * 32 + s];
            float sc;
            if (cde == 0) {
                const float4* X4 = (const float4*)&Xbuf[s * XSTR];
                const float4* P4 = (const float4*)&PY[(g * 8 + h) * PSTR];
                float a0 = 0.f, a1 = 0.f;
#pragma unroll
                for (int j = 0; j < 24; j += 2) {
                    float4 x0 = X4[j * 4 + q],       p0 = P4[j * 4 + q];
                    float4 x1 = X4[(j + 1) * 4 + q], p1 = P4[(j + 1) * 4 + q];
                    a0 = fmaf(x0.x, p0.x, fmaf(x0.y, p0.y, fmaf(x0.z, p0.z, fmaf(x0.w, p0.w, a0))));
                    a1 = fmaf(x1.x, p1.x, fmaf(x1.y, p1.y, fmaf(x1.z, p1.z, fmaf(x1.w, p1.w, a1))));
                }
                float a = a0 + a1;
                a += __shfl_xor_sync(0xffffffffu, a, 1);
                a += __shfl_xor_sync(0xffffffffu, a, 2);
                sc = a * 0.17677669529663687f;
            } else {
                sc = (cde == 1) ? -1e10f : 0.f;
            }
            if (q == 0) Att[s * 9 + h] = sc;
        }
        __syncthreads();

        // softmax: warp h owns head h
        if (wid < 8) {
            float v = Att[lane * 9 + wid];
            float mx = wmax(v);
            float e = __expf(v - mx);
            float ss = wsum(e);
            Wt[wid * 32 + lane] = e / ss;
        }
        __syncthreads();

        // Y[g][h][col + 128k]
        {
            const int h = t >> 7, col = t & 127;
            const float* Wrow = &Wt[h * 32];
            float a0 = 0.f, a1 = 0.f, a2 = 0.f;
#pragma unroll 1
            for (int s = 0; s < 32; ++s) {
                float w = Wrow[s];
                if (w != 0.f) {
                    const float* xr = &Xbuf[s * XSTR + col];
                    a0 = fmaf(w, xr[0],   a0);
                    a1 = fmaf(w, xr[128], a1);
                    a2 = fmaf(w, xr[256], a2);
                }
            }
            float* yr = &PY[(g * 8 + h) * PSTR + col];
            yr[0] = a0; yr[128] = a1; yr[256] = a2;
        }
        cpwaitall();
        __syncthreads();
    }

    // ---- phase 4: O[g][o] partials over i-quarters (stage in XS buf0) ----
    {
        const int o = t & 255, q = t >> 8, h = o >> 5;
        float acc[8];
#pragma unroll
        for (int g = 0; g < 8; ++g) acc[g] = 0.f;
        const float* wvp = WKV + 256 + o;
        const int i0 = q * 96;
#pragma unroll 2
        for (int j = 0; j < 24; ++j) {
            int i = i0 + j * 4;
            float w0 = __ldg(&wvp[(size_t)(i + 0) * 512]);
            float w1 = __ldg(&wvp[(size_t)(i + 1) * 512]);
            float w2 = __ldg(&wvp[(size_t)(i + 2) * 512]);
            float w3 = __ldg(&wvp[(size_t)(i + 3) * 512]);
#pragma unroll
            for (int g = 0; g < 8; ++g) {
                float4 y = *(const float4*)&PY[(g * 8 + h) * PSTR + i];
                acc[g] = fmaf(y.x, w0, fmaf(y.y, w1, fmaf(y.z, w2, fmaf(y.w, w3, acc[g]))));
            }
        }
        float* stg = XS + q * 2048 + o * 8;
        *(float4*)stg       = make_float4(acc[0], acc[1], acc[2], acc[3]);
        *(float4*)(stg + 4) = make_float4(acc[4], acc[5], acc[6], acc[7]);
    }
    __syncthreads();
    {
#pragma unroll
        for (int r = 0; r < 2; ++r) {
            int idx = r * 1024 + t;
            float s = XS[idx] + XS[2048 + idx] + XS[4096 + idx] + XS[6144 + idx];
            Qs[idx] = s;   // OvT layout [o][g]
        }
    }
    __syncthreads();

    // ---- phase 5: out = OvT @ WO + bO + R, LN (stage in XS1) ----
    {
        const int o = t & 255, q = t >> 8;
        float acc[8];
#pragma unroll
        for (int g = 0; g < 8; ++g) acc[g] = 0.f;
        const int i0 = q * 64;
#pragma unroll 4
        for (int ii = 0; ii < 64; ++ii) {
            int i = i0 + ii;
            float wo = __ldg(&WO[i * 256 + o]);
            float4 v0 = *(const float4*)&Qs[i * 8];
            float4 v1 = *(const float4*)&Qs[i * 8 + 4];
            acc[0] = fmaf(v0.x, wo, acc[0]);
            acc[1] = fmaf(v0.y, wo, acc[1]);
            acc[2] = fmaf(v0.z, wo, acc[2]);
            acc[3] = fmaf(v0.w, wo, acc[3]);
            acc[4] = fmaf(v1.x, wo, acc[4]);
            acc[5] = fmaf(v1.y, wo, acc[5]);
            acc[6] = fmaf(v1.z, wo, acc[6]);
            acc[7] = fmaf(v1.w, wo, acc[7]);
        }
        float* stg = XS1 + q * 2048 + o * 8;
        *(float4*)stg       = make_float4(acc[0], acc[1], acc[2], acc[3]);
        *(float4*)(stg + 4) = make_float4(acc[4], acc[5], acc[6], acc[7]);
    }
    __syncthreads();
    {
        const int o = t & 255, gp = t >> 8;   // gp selects g-pair {2gp, 2gp+1}
        float xg[2];
#pragma unroll
        for (int j = 0; j < 2; ++j) {
            int g = gp * 2 + j;
            int idx = o * 8 + g;
            float s = XS1[idx] + XS1[2048 + idx] + XS1[4096 + idx] + XS1[6144 + idx];
            xg[j] = s + __ldg(&bO[o]) + RT[o * 8 + g];
            float s1 = wsum(xg[j]);
            float s2 = wsum(xg[j] * xg[j]);
            if (lane == 0) { red1[wid * 2 + j] = s1; red2[wid * 2 + j] = s2; }
        }
        __syncthreads();
        if (t < 8) {
            int g = t, gq = g >> 1, j = g & 1;
            float t1 = 0.f, t2 = 0.f;
#pragma unroll
            for (int w = 0; w < 8; ++w) {
                t1 += red1[(gq * 8 + w) * 2 + j];
                t2 += red2[(gq * 8 + w) * 2 + j];
            }
            float mu = t1 * (1.0f / 256.0f);
            float var = t2 * (1.0f / 256.0f) - mu * mu;
            muS[g] = mu;
            rsS[g] = rsqrtf(var + 1e-5f);
        }
        __syncthreads();
        float gm = __ldg(&gamma[o]), bt = __ldg(&beta[o]);
#pragma unroll
        for (int j = 0; j < 2; ++j) {
            int g = gp * 2 + j;
            int b = b0 + g;
            if (b < B)
                out[(size_t)b * 256 + o] = (xg[j] - muS[g]) * rsS[g] * gm + bt;
        }
    }
}

extern "C" void kernel_launch(void* const* d_in, const int* in_sizes, int n_in,
                              void* d_out, int out_size) {
    (void)n_in; (void)out_size;
    const float* node  = (const float*)d_in[0];
    const float* timef = (const float*)d_in[1];
    const float* edge  = (const float*)d_in[2];
    const float* nnode = (const float*)d_in[3];
    const float* ntime = (const float*)d_in[4];
    const int*   mask  = (const int*)d_in[5];
    const float* WQ    = (const float*)d_in[6];
    const float* WKV   = (const float*)d_in[7];
    const float* WO    = (const float*)d_in[8];
    const float* bO    = (const float*)d_in[9];
    const float* gamma = (const float*)d_in[10];
    const float* beta  = (const float*)d_in[11];
    float* out = (float*)d_out;

    int B = in_sizes[0] / 128;
    int blocks = (B + G - 1) / G;

    cudaFuncSetAttribute(ta_kernel, cudaFuncAttributeMaxDynamicSharedMemorySize, SMEM_BYTES);
    ta_kernel<<<blocks, NT, SMEM_BYTES>>>(node, timef, edge, nnode, ntime, mask,
                                          WQ, WKV, WO, bO, gamma, beta, out, B);
}

// round 5
// speedup vs baseline: 1.6600x; 1.1141x over previous
#include <cuda_runtime.h>
#include <math.h>

typedef unsigned long long ull;

#define G    8
#define NT   1024
#define XSTR 388
#define PSTR 388

#define RT_OFF   0                        // [256][8]
#define QS_OFF   2048                     // Q as [o][g], later OvT [o][g]
#define PY_OFF   4096                     // [8g][8h][388]
#define XS_OFF   (PY_OFF + 24832)         // 2 x [32][388]
#define XS1_OFF  (XS_OFF + 12416)
#define AT_OFF   (XS_OFF + 24832)         // [32][9]
#define WT2_OFF  (AT_OFF + 288)           // [4 hp][32 s] float2 = 256 floats
#define RD1_OFF  (WT2_OFF + 256)          // [32][2]
#define RD2_OFF  (RD1_OFF + 64)
#define MU_OFF   (RD2_OFF + 64)
#define RS_OFF   (MU_OFF + 8)
#define CODE_OFF (RS_OFF + 8)             // [8][32] ints
#define SMEM_FLOATS (CODE_OFF + 256)
#define SMEM_BYTES  (SMEM_FLOATS * 4)

__device__ __forceinline__ float wsum(float v) {
#pragma unroll
    for (int o = 16; o > 0; o >>= 1) v += __shfl_xor_sync(0xffffffffu, v, o);
    return v;
}
__device__ __forceinline__ float wmax(float v) {
#pragma unroll
    for (int o = 16; o > 0; o >>= 1) v = fmaxf(v, __shfl_xor_sync(0xffffffffu, v, o));
    return v;
}
__device__ __forceinline__ void fma2(ull& d, ull a, ull b) {
    asm("fma.rn.f32x2 %0, %1, %2, %0;" : "+l"(d) : "l"(a), "l"(b));
}
__device__ __forceinline__ ull add2(ull a, ull b) {
    ull r; asm("add.rn.f32x2 %0, %1, %2;" : "=l"(r) : "l"(a), "l"(b)); return r;
}
__device__ __forceinline__ ull pack2(float v) {
    ull r; asm("mov.b64 %0, {%1, %1};" : "=l"(r) : "r"(__float_as_uint(v))); return r;
}
__device__ __forceinline__ ull pk(float a, float b) {
    ull r; asm("mov.b64 %0, {%1, %2};" : "=l"(r) : "r"(__float_as_uint(a)), "r"(__float_as_uint(b))); return r;
}
__device__ __forceinline__ float2 unpk(ull a) {
    float2 f; asm("mov.b64 {%0, %1}, %2;" : "=f"(f.x), "=f"(f.y) : "l"(a)); return f;
}
__device__ __forceinline__ float sum2(ull a) { float2 f = unpk(a); return f.x + f.y; }

__device__ __forceinline__ void cpasync16(void* dst, const void* src) {
    unsigned d = (unsigned)__cvta_generic_to_shared(dst);
    asm volatile("cp.async.cg.shared.global [%0], [%1], 16;\n" :: "r"(d), "l"(src));
}
__device__ __forceinline__ void cpcommit() {
    asm volatile("cp.async.commit_group;\n" ::: "memory");
}
__device__ __forceinline__ void cpwaitall() {
    asm volatile("cp.async.wait_group 0;\n" ::: "memory");
}

__device__ __forceinline__ void prefetchX(float* Xbuf, long long b,
                                          const float4* nn4, const float4* ed4, const float4* et4,
                                          int start, int stride) {
    for (int idx = start; idx < 3072; idx += stride) {
        int s = idx / 96, c4 = idx - s * 96;
        long long rb = (b * 32 + s) * 32;
        const float4* src = (c4 < 32) ? nn4 + rb + c4
                          : (c4 < 64) ? ed4 + rb + (c4 - 32)
                                      : et4 + rb + (c4 - 64);
        cpasync16(&Xbuf[s * XSTR + c4 * 4], src);
    }
}

__global__ __launch_bounds__(NT, 1)
void ta_kernel(const float* __restrict__ node,
               const float* __restrict__ timef,
               const float* __restrict__ edge,
               const float* __restrict__ nnode,
               const float* __restrict__ ntime,
               const int* __restrict__ mask,
               const float* __restrict__ WQ,
               const float* __restrict__ WKV,
               const float* __restrict__ WO,
               const float* __restrict__ bO,
               const float* __restrict__ gamma,
               const float* __restrict__ beta,
               float* __restrict__ out,
               int B)
{
    extern __shared__ float smf[];
    float* RT   = smf + RT_OFF;
    float* Qs   = smf + QS_OFF;      // [o][g]; later OvT [o][g]
    float* PY   = smf + PY_OFF;
    float* XS   = smf + XS_OFF;
    float* XS1  = smf + XS1_OFF;
    float* Att  = smf + AT_OFF;
    float* Wt2  = smf + WT2_OFF;
    float* red1 = smf + RD1_OFF;
    float* red2 = smf + RD2_OFF;
    float* muS  = smf + MU_OFF;
    float* rsS  = smf + RS_OFF;
    int*   codeS = (int*)(smf + CODE_OFF);

    const int t = threadIdx.x;
    const int wid = t >> 5, lane = t & 31;
    const int b0 = blockIdx.x * G;

    const float4* nn4 = (const float4*)nnode;
    const float4* ed4 = (const float4*)edge;
    const float4* et4 = (const float4*)ntime;

    // prefetch X[g=0] (overlaps phases 0-2)
    {
        int bb = b0; if (bb > B - 1) bb = B - 1;
        prefetchX(XS, (long long)bb, nn4, ed4, et4, t, NT);
        cpcommit();
    }

    // ---- phase 0: RT + mask codes ----
    for (int idx = t; idx < G * 256; idx += NT) {
        int g = idx & 7, j = idx >> 3;
        int bb = b0 + g; if (bb > B - 1) bb = B - 1;
        long long b = bb;
        float v = (j < 128) ? node[b * 128 + j] : timef[b * 128 + (j - 128)];
        RT[j * G + g] = v;
    }
    if (t < 256) {
        int g = wid;
        int bb = b0 + g; if (bb > B - 1) bb = B - 1;
        int mk = mask[(long long)bb * 32 + lane];
        unsigned bal = __ballot_sync(0xffffffffu, mk != 0);
        codeS[g * 32 + lane] = (bal == 0u) ? 2 : (mk ? 0 : 1);
    }
    __syncthreads();

    // ---- phase 1: Q partials (packed g-pairs), staged in XS1 ----
    {
        const int o = t & 255, q = t >> 8;
        ull a0 = 0, a1 = 0, a2 = 0, a3 = 0;
        const int i0 = q * 64;
        const ull* RT2 = (const ull*)RT;
#pragma unroll 4
        for (int ii = 0; ii < 64; ++ii) {
            int i = i0 + ii;
            ull w2 = pack2(__ldg(&WQ[i * 256 + o]));
            ulonglong2 ra = *(const ulonglong2*)&RT2[i * 4];
            ulonglong2 rb = *(const ulonglong2*)&RT2[i * 4 + 2];
            fma2(a0, ra.x, w2); fma2(a1, ra.y, w2);
            fma2(a2, rb.x, w2); fma2(a3, rb.y, w2);
        }
        ull* stg = (ull*)(XS1 + q * 2048 + o * 8);
        ((ulonglong2*)stg)[0] = make_ulonglong2(a0, a1);
        ((ulonglong2*)stg)[1] = make_ulonglong2(a2, a3);
    }
    __syncthreads();
    {
        const ull* S = (const ull*)XS1;
        ull s = add2(add2(S[t], S[1024 + t]), add2(S[2048 + t], S[3072 + t]));
        ((ull*)Qs)[t] = s;      // Q in [o][g] layout
    }
    __syncthreads();

    // ---- phase 2: P[g][h][i] (packed g-pairs) ----
#pragma unroll 1
    for (int k = 0; k < 3; ++k) {
        int flat = k * NT + t;            // 0..3071 over (h,i)
        int h = flat / 384;
        int i = flat - h * 384;
        const float4* wk4 = (const float4*)(WKV + (size_t)i * 512 + h * 32);
        const ull* Q2 = (const ull*)Qs;
        ull a0 = 0, a1 = 0, a2 = 0, a3 = 0;
#pragma unroll
        for (int d4 = 0; d4 < 8; ++d4) {
            float4 w = __ldg(&wk4[d4]);
#pragma unroll
            for (int d = 0; d < 4; ++d) {
                ull wp = pack2((&w.x)[d]);
                int ob = (h * 32 + d4 * 4 + d) * 4;
                ulonglong2 qa = *(const ulonglong2*)&Q2[ob];
                ulonglong2 qb = *(const ulonglong2*)&Q2[ob + 2];
                fma2(a0, qa.x, wp); fma2(a1, qa.y, wp);
                fma2(a2, qb.x, wp); fma2(a3, qb.y, wp);
            }
        }
        float2 f0 = unpk(a0), f1 = unpk(a1), f2 = unpk(a2), f3 = unpk(a3);
        PY[(0 * 8 + h) * PSTR + i] = f0.x;
        PY[(1 * 8 + h) * PSTR + i] = f0.y;
        PY[(2 * 8 + h) * PSTR + i] = f1.x;
        PY[(3 * 8 + h) * PSTR + i] = f1.y;
        PY[(4 * 8 + h) * PSTR + i] = f2.x;
        PY[(5 * 8 + h) * PSTR + i] = f2.y;
        PY[(6 * 8 + h) * PSTR + i] = f3.x;
        PY[(7 * 8 + h) * PSTR + i] = f3.y;
    }
    cpwaitall();
    __syncthreads();

    // ---- phase 3: per-g attention ----
#pragma unroll 1
    for (int g = 0; g < G; ++g) {
        float* Xbuf = XS + (g & 1) * 12416;

        if (g < G - 1) {
            int bb = b0 + g + 1; if (bb > B - 1) bb = B - 1;
            prefetchX(XS + ((g + 1) & 1) * 12416, (long long)bb, nn4, ed4, et4, t, NT);
        }
        cpcommit();

        // scores: warp = s, lanes = (h, q); packed over i
        {
            const int s = wid;
            const int h = lane >> 2, q = lane & 3;
            int cde = codeS[g * 32 + s];
            float sc;
            if (cde == 0) {
                const ulonglong2* X2 = (const ulonglong2*)&Xbuf[s * XSTR];
                const ulonglong2* P2 = (const ulonglong2*)&PY[(g * 8 + h) * PSTR];
                ull a0 = 0, a1 = 0;
#pragma unroll
                for (int j = 0; j < 24; ++j) {
                    ulonglong2 x = X2[j * 4 + q];
                    ulonglong2 p = P2[j * 4 + q];
                    fma2(a0, x.x, p.x);
                    fma2(a1, x.y, p.y);
                }
                float a = sum2(a0) + sum2(a1);
                a += __shfl_xor_sync(0xffffffffu, a, 1);
                a += __shfl_xor_sync(0xffffffffu, a, 2);
                sc = a * 0.17677669529663687f;
            } else {
                sc = (cde == 1) ? -1e10f : 0.f;
            }
            if (q == 0) Att[s * 9 + h] = sc;
        }
        __syncthreads();

        // softmax: warp h owns head h; writes packed h-pair weights
        if (wid < 8) {
            float v = Att[lane * 9 + wid];
            float mx = wmax(v);
            float e = __expf(v - mx);
            float ss = wsum(e);
            Wt2[((wid >> 1) * 32 + lane) * 2 + (wid & 1)] = e / ss;
        }
        __syncthreads();

        // Y[g][h][col]: thread = (h-half, col), 4 heads packed as 2 f32x2
        if (t < 768) {
            const int hh = (t >= 384) ? 1 : 0;
            const int col = t - hh * 384;
            const ull* W2 = (const ull*)Wt2;
            ull acc0 = 0, acc1 = 0;
#pragma unroll 4
            for (int s = 0; s < 32; ++s) {
                ull x2 = pack2(Xbuf[s * XSTR + col]);
                fma2(acc0, x2, W2[(hh * 2 + 0) * 32 + s]);
                fma2(acc1, x2, W2[(hh * 2 + 1) * 32 + s]);
            }
            float2 y01 = unpk(acc0), y23 = unpk(acc1);
            PY[(g * 8 + hh * 4 + 0) * PSTR + col] = y01.x;
            PY[(g * 8 + hh * 4 + 1) * PSTR + col] = y01.y;
            PY[(g * 8 + hh * 4 + 2) * PSTR + col] = y23.x;
            PY[(g * 8 + hh * 4 + 3) * PSTR + col] = y23.y;
        }
        cpwaitall();
        __syncthreads();
    }

    // ---- phase 4: O partials (packed i-pairs per g), staged in XS ----
    {
        const int o = t & 255, q = t >> 8, h = o >> 5;
        ull acc2[8];
#pragma unroll
        for (int g = 0; g < 8; ++g) acc2[g] = 0;
        const float* wvp = WKV + 256 + o;
        const int i0 = q * 96;
#pragma unroll 2
        for (int j = 0; j < 24; ++j) {
            int i = i0 + j * 4;
            float w0 = __ldg(&wvp[(size_t)(i + 0) * 512]);
            float w1 = __ldg(&wvp[(size_t)(i + 1) * 512]);
            float w2 = __ldg(&wvp[(size_t)(i + 2) * 512]);
            float w3 = __ldg(&wvp[(size_t)(i + 3) * 512]);
            ull wp01 = pk(w0, w1), wp23 = pk(w2, w3);
#pragma unroll
            for (int g = 0; g < 8; ++g) {
                ulonglong2 y = *(const ulonglong2*)&PY[(g * 8 + h) * PSTR + i];
                fma2(acc2[g], y.x, wp01);
                fma2(acc2[g], y.y, wp23);
            }
        }
        float r[8];
#pragma unroll
        for (int g = 0; g < 8; ++g) r[g] = sum2(acc2[g]);
        float* stg = XS + q * 2048 + o * 8;
        *(float4*)stg       = make_float4(r[0], r[1], r[2], r[3]);
        *(float4*)(stg + 4) = make_float4(r[4], r[5], r[6], r[7]);
    }
    __syncthreads();
    {
        const ull* S = (const ull*)XS;
        ull s = add2(add2(S[t], S[1024 + t]), add2(S[2048 + t], S[3072 + t]));
        ((ull*)Qs)[t] = s;     // OvT in [o][g] layout
    }
    __syncthreads();

    // ---- phase 5: out-proj partials (packed g-pairs), staged in XS1 ----
    {
        const int o = t & 255, q = t >> 8;
        ull a0 = 0, a1 = 0, a2 = 0, a3 = 0;
        const ull* O2 = (const ull*)Qs;
        const int i0 = q * 64;
#pragma unroll 4
        for (int ii = 0; ii < 64; ++ii) {
            int i = i0 + ii;
            ull wp = pack2(__ldg(&WO[i * 256 + o]));
            ulonglong2 va = *(const ulonglong2*)&O2[i * 4];
            ulonglong2 vb = *(const ulonglong2*)&O2[i * 4 + 2];
            fma2(a0, va.x, wp); fma2(a1, va.y, wp);
            fma2(a2, vb.x, wp); fma2(a3, vb.y, wp);
        }
        float2 f0 = unpk(a0), f1 = unpk(a1), f2 = unpk(a2), f3 = unpk(a3);
        float* stg = XS1 + q * 2048 + o * 8;
        *(float4*)stg       = make_float4(f0.x, f0.y, f1.x, f1.y);
        *(float4*)(stg + 4) = make_float4(f2.x, f2.y, f3.x, f3.y);
    }
    __syncthreads();

    // ---- final: residual + LayerNorm ----
    {
        const int o = t & 255, gp = t >> 8;
        float xg[2];
#pragma unroll
        for (int j = 0; j < 2; ++j) {
            int g = gp * 2 + j;
            int idx = o * 8 + g;
            float s = XS1[idx] + XS1[2048 + idx] + XS1[4096 + idx] + XS1[6144 + idx];
            xg[j] = s + __ldg(&bO[o]) + RT[o * 8 + g];
            float s1 = wsum(xg[j]);
            float s2 = wsum(xg[j] * xg[j]);
            if (lane == 0) { red1[wid * 2 + j] = s1; red2[wid * 2 + j] = s2; }
        }
        __syncthreads();
        if (t < 8) {
            int g = t, gq = g >> 1, j = g & 1;
            float t1 = 0.f, t2 = 0.f;
#pragma unroll
            for (int w = 0; w < 8; ++w) {
                t1 += red1[(gq * 8 + w) * 2 + j];
                t2 += red2[(gq * 8 + w) * 2 + j];
            }
            float mu = t1 * (1.0f / 256.0f);
            float var = t2 * (1.0f / 256.0f) - mu * mu;
            muS[g] = mu;
            rsS[g] = rsqrtf(var + 1e-5f);
        }
        __syncthreads();
        float gm = __ldg(&gamma[o]), bt = __ldg(&beta[o]);
#pragma unroll
        for (int j = 0; j < 2; ++j) {
            int g = gp * 2 + j;
            int b = b0 + g;
            if (b < B)
                out[(size_t)b * 256 + o] = (xg[j] - muS[g]) * rsS[g] * gm + bt;
        }
    }
}

extern "C" void kernel_launch(void* const* d_in, const int* in_sizes, int n_in,
                              void* d_out, int out_size) {
    (void)n_in; (void)out_size;
    const float* node  = (const float*)d_in[0];
    const float* timef = (const float*)d_in[1];
    const float* edge  = (const float*)d_in[2];
    const float* nnode = (const float*)d_in[3];
    const float* ntime = (const float*)d_in[4];
    const int*   mask  = (const int*)d_in[5];
    const float* WQ    = (const float*)d_in[6];
    const float* WKV   = (const float*)d_in[7];
    const float* WO    = (const float*)d_in[8];
    const float* bO    = (const float*)d_in[9];
    const float* gamma = (const float*)d_in[10];
    const float* beta  = (const float*)d_in[11];
    float* out = (float*)d_out;

    int B = in_sizes[0] / 128;
    int blocks = (B + G - 1) / G;

    cudaFuncSetAttribute(ta_kernel, cudaFuncAttributeMaxDynamicSharedMemorySize, SMEM_BYTES);
    ta_kernel<<<blocks, NT, SMEM_BYTES>>>(node, timef, edge, nnode, ntime, mask,
                                          WQ, WKV, WO, bO, gamma, beta, out, B);
}

// round 6
// speedup vs baseline: 1.7712x; 1.0669x over previous
#include <cuda_runtime.h>
#include <math.h>

typedef unsigned long long ull;

#define G    8
#define NT   1024
#define XSTR 388
#define PSTR 388

#define RT_OFF   0                        // [256][8]
#define QS_OFF   2048                     // Q as [o][g]; AttP during phase 3; OvT after
#define PY_OFF   4096                     // [8g][8h][388]
#define XS_OFF   (PY_OFF + 24832)         // 2 x [32][388]
#define XS1_OFF  (XS_OFF + 12416)
#define WT2_OFF  (XS_OFF + 24832)         // [4 hp][32 s] float2 = 256 floats
#define RD1_OFF  (WT2_OFF + 256)          // [32][2]
#define RD2_OFF  (RD1_OFF + 64)
#define MU_OFF   (RD2_OFF + 64)
#define RS_OFF   (MU_OFF + 8)
#define CODE_OFF (RS_OFF + 8)             // [8][32] ints
#define SMEM_FLOATS (CODE_OFF + 256)
#define SMEM_BYTES  (SMEM_FLOATS * 4)

__device__ __forceinline__ float wsum(float v) {
#pragma unroll
    for (int o = 16; o > 0; o >>= 1) v += __shfl_xor_sync(0xffffffffu, v, o);
    return v;
}
__device__ __forceinline__ float wmax(float v) {
#pragma unroll
    for (int o = 16; o > 0; o >>= 1) v = fmaxf(v, __shfl_xor_sync(0xffffffffu, v, o));
    return v;
}
__device__ __forceinline__ void fma2(ull& d, ull a, ull b) {
    asm("fma.rn.f32x2 %0, %1, %2, %0;" : "+l"(d) : "l"(a), "l"(b));
}
__device__ __forceinline__ ull add2(ull a, ull b) {
    ull r; asm("add.rn.f32x2 %0, %1, %2;" : "=l"(r) : "l"(a), "l"(b)); return r;
}
__device__ __forceinline__ ull pack2(float v) {
    ull r; asm("mov.b64 %0, {%1, %1};" : "=l"(r) : "r"(__float_as_uint(v))); return r;
}
__device__ __forceinline__ ull pk(float a, float b) {
    ull r; asm("mov.b64 %0, {%1, %2};" : "=l"(r) : "r"(__float_as_uint(a)), "r"(__float_as_uint(b))); return r;
}
__device__ __forceinline__ float2 unpk(ull a) {
    float2 f; asm("mov.b64 {%0, %1}, %2;" : "=f"(f.x), "=f"(f.y) : "l"(a)); return f;
}
__device__ __forceinline__ float sum2(ull a) { float2 f = unpk(a); return f.x + f.y; }

__device__ __forceinline__ void cpasync16(void* dst, const void* src) {
    unsigned d = (unsigned)__cvta_generic_to_shared(dst);
    asm volatile("cp.async.cg.shared.global [%0], [%1], 16;\n" :: "r"(d), "l"(src));
}
__device__ __forceinline__ void cpcommit() {
    asm volatile("cp.async.commit_group;\n" ::: "memory");
}
__device__ __forceinline__ void cpwaitall() {
    asm volatile("cp.async.wait_group 0;\n" ::: "memory");
}

__device__ __forceinline__ void prefetchX(float* Xbuf, long long b,
                                          const float4* nn4, const float4* ed4, const float4* et4,
                                          int start, int stride) {
    for (int idx = start; idx < 3072; idx += stride) {
        int s = idx / 96, c4 = idx - s * 96;
        long long rb = (b * 32 + s) * 32;
        const float4* src = (c4 < 32) ? nn4 + rb + c4
                          : (c4 < 64) ? ed4 + rb + (c4 - 32)
                                      : et4 + rb + (c4 - 64);
        cpasync16(&Xbuf[s * XSTR + c4 * 4], src);
    }
}

__global__ __launch_bounds__(NT, 1)
void ta_kernel(const float* __restrict__ node,
               const float* __restrict__ timef,
               const float* __restrict__ edge,
               const float* __restrict__ nnode,
               const float* __restrict__ ntime,
               const int* __restrict__ mask,
               const float* __restrict__ WQ,
               const float* __restrict__ WKV,
               const float* __restrict__ WO,
               const float* __restrict__ bO,
               const float* __restrict__ gamma,
               const float* __restrict__ beta,
               float* __restrict__ out,
               int B)
{
    extern __shared__ float smf[];
    float* RT   = smf + RT_OFF;
    float* Qs   = smf + QS_OFF;      // Q [o][g]; AttP [4][32][8] in phase 3; OvT [o][g] after
    float* PY   = smf + PY_OFF;
    float* XS   = smf + XS_OFF;
    float* XS1  = smf + XS1_OFF;
    float* Wt2  = smf + WT2_OFF;
    float* red1 = smf + RD1_OFF;
    float* red2 = smf + RD2_OFF;
    float* muS  = smf + MU_OFF;
    float* rsS  = smf + RS_OFF;
    int*   codeS = (int*)(smf + CODE_OFF);

    const int t = threadIdx.x;
    const int wid = t >> 5, lane = t & 31;
    const int b0 = blockIdx.x * G;

    const float4* nn4 = (const float4*)nnode;
    const float4* ed4 = (const float4*)edge;
    const float4* et4 = (const float4*)ntime;

    // prefetch X[g=0] (overlaps phases 0-2)
    {
        int bb = b0; if (bb > B - 1) bb = B - 1;
        prefetchX(XS, (long long)bb, nn4, ed4, et4, t, NT);
        cpcommit();
    }

    // ---- phase 0: RT + mask codes ----
    for (int idx = t; idx < G * 256; idx += NT) {
        int g = idx & 7, j = idx >> 3;
        int bb = b0 + g; if (bb > B - 1) bb = B - 1;
        long long b = bb;
        float v = (j < 128) ? node[b * 128 + j] : timef[b * 128 + (j - 128)];
        RT[j * G + g] = v;
    }
    if (t < 256) {
        int g = wid;
        int bb = b0 + g; if (bb > B - 1) bb = B - 1;
        int mk = mask[(long long)bb * 32 + lane];
        unsigned bal = __ballot_sync(0xffffffffu, mk != 0);
        codeS[g * 32 + lane] = (bal == 0u) ? 2 : (mk ? 0 : 1);
    }
    __syncthreads();

    // ---- phase 1: Q partials (packed g-pairs), staged in XS1 ----
    {
        const int o = t & 255, q = t >> 8;
        ull a0 = 0, a1 = 0, a2 = 0, a3 = 0;
        const int i0 = q * 64;
        const ull* RT2 = (const ull*)RT;
#pragma unroll 4
        for (int ii = 0; ii < 64; ++ii) {
            int i = i0 + ii;
            ull w2 = pack2(__ldg(&WQ[i * 256 + o]));
            ulonglong2 ra = *(const ulonglong2*)&RT2[i * 4];
            ulonglong2 rb = *(const ulonglong2*)&RT2[i * 4 + 2];
            fma2(a0, ra.x, w2); fma2(a1, ra.y, w2);
            fma2(a2, rb.x, w2); fma2(a3, rb.y, w2);
        }
        ull* stg = (ull*)(XS1 + q * 2048 + o * 8);
        ((ulonglong2*)stg)[0] = make_ulonglong2(a0, a1);
        ((ulonglong2*)stg)[1] = make_ulonglong2(a2, a3);
    }
    __syncthreads();
    {
        const ull* S = (const ull*)XS1;
        ull s = add2(add2(S[t], S[1024 + t]), add2(S[2048 + t], S[3072 + t]));
        ((ull*)Qs)[t] = s;      // Q in [o][g] layout
    }
    __syncthreads();

    // ---- phase 2: P[g][h][i] (packed g-pairs) ----
#pragma unroll 1
    for (int k = 0; k < 3; ++k) {
        int flat = k * NT + t;            // 0..3071 over (h,i)
        int h = flat / 384;
        int i = flat - h * 384;
        const float4* wk4 = (const float4*)(WKV + (size_t)i * 512 + h * 32);
        const ull* Q2 = (const ull*)Qs;
        ull a0 = 0, a1 = 0, a2 = 0, a3 = 0;
#pragma unroll
        for (int d4 = 0; d4 < 8; ++d4) {
            float4 w = __ldg(&wk4[d4]);
#pragma unroll
            for (int d = 0; d < 4; ++d) {
                ull wp = pack2((&w.x)[d]);
                int ob = (h * 32 + d4 * 4 + d) * 4;
                ulonglong2 qa = *(const ulonglong2*)&Q2[ob];
                ulonglong2 qb = *(const ulonglong2*)&Q2[ob + 2];
                fma2(a0, qa.x, wp); fma2(a1, qa.y, wp);
                fma2(a2, qb.x, wp); fma2(a3, qb.y, wp);
            }
        }
        float2 f0 = unpk(a0), f1 = unpk(a1), f2 = unpk(a2), f3 = unpk(a3);
        PY[(0 * 8 + h) * PSTR + i] = f0.x;
        PY[(1 * 8 + h) * PSTR + i] = f0.y;
        PY[(2 * 8 + h) * PSTR + i] = f1.x;
        PY[(3 * 8 + h) * PSTR + i] = f1.y;
        PY[(4 * 8 + h) * PSTR + i] = f2.x;
        PY[(5 * 8 + h) * PSTR + i] = f2.y;
        PY[(6 * 8 + h) * PSTR + i] = f3.x;
        PY[(7 * 8 + h) * PSTR + i] = f3.y;
    }
    cpwaitall();
    __syncthreads();

    // ---- phase 3: per-g attention ----
    float* AttP = Qs;    // [4 iq][32 s][8 h] partials (Q is dead now)
#pragma unroll 1
    for (int g = 0; g < G; ++g) {
        float* Xbuf = XS + (g & 1) * 12416;

        if (g < G - 1) {
            int bb = b0 + g + 1; if (bb > B - 1) bb = B - 1;
            prefetchX(XS + ((g + 1) & 1) * 12416, (long long)bb, nn4, ed4, et4, t, NT);
        }
        cpcommit();

        // scores: warp = (s-quad, i-quarter); lane = (h, s-local)
        {
            const int sq = wid >> 2, iq = wid & 3;
            const int h = lane >> 2, sl = lane & 3;
            const int s = sq * 4 + sl;
            const int cde = codeS[g * 32 + s];
            const unsigned act = __ballot_sync(0xffffffffu, cde == 0);
            ull a0 = 0, a1 = 0;
            if (act) {
                const ulonglong2* X2 = (const ulonglong2*)&Xbuf[s * XSTR + iq * 96];
                const ulonglong2* P2 = (const ulonglong2*)&PY[(g * 8 + h) * PSTR + iq * 96];
#pragma unroll
                for (int j = 0; j < 24; j += 2) {
                    ulonglong2 p0 = P2[j];
                    ulonglong2 p1 = P2[j + 1];
                    if (cde == 0) {
                        ulonglong2 x0 = X2[j];
                        ulonglong2 x1 = X2[j + 1];
                        fma2(a0, x0.x, p0.x); fma2(a0, x0.y, p0.y);
                        fma2(a1, x1.x, p1.x); fma2(a1, x1.y, p1.y);
                    }
                }
            }
            AttP[iq * 256 + s * 8 + h] = sum2(add2(a0, a1));
        }
        __syncthreads();

        // softmax: warp h (wid<8), lane = s; reduce 4 i-quarter partials
        if (wid < 8) {
            const int s = lane;
            int cde = codeS[g * 32 + s];
            float a = AttP[s * 8 + wid] + AttP[256 + s * 8 + wid]
                    + AttP[512 + s * 8 + wid] + AttP[768 + s * 8 + wid];
            float v = (cde == 0) ? a * 0.17677669529663687f
                                 : ((cde == 1) ? -1e10f : 0.f);
            float mx = wmax(v);
            float e = __expf(v - mx);
            float ss = wsum(e);
            Wt2[((wid >> 1) * 32 + s) * 2 + (wid & 1)] = e / ss;
        }
        __syncthreads();

        // Y[g][*][col]: thread = col (384 threads), all 8 heads packed
        if (t < 384) {
            const int col = t;
            const ull* W2 = (const ull*)Wt2;
            ull acc0 = 0, acc1 = 0, acc2 = 0, acc3 = 0;
#pragma unroll 4
            for (int s = 0; s < 32; ++s) {
                ull x2 = pack2(Xbuf[s * XSTR + col]);
                fma2(acc0, x2, W2[0 * 32 + s]);
                fma2(acc1, x2, W2[1 * 32 + s]);
                fma2(acc2, x2, W2[2 * 32 + s]);
                fma2(acc3, x2, W2[3 * 32 + s]);
            }
            float2 y01 = unpk(acc0), y23 = unpk(acc1);
            float2 y45 = unpk(acc2), y67 = unpk(acc3);
            PY[(g * 8 + 0) * PSTR + col] = y01.x;
            PY[(g * 8 + 1) * PSTR + col] = y01.y;
            PY[(g * 8 + 2) * PSTR + col] = y23.x;
            PY[(g * 8 + 3) * PSTR + col] = y23.y;
            PY[(g * 8 + 4) * PSTR + col] = y45.x;
            PY[(g * 8 + 5) * PSTR + col] = y45.y;
            PY[(g * 8 + 6) * PSTR + col] = y67.x;
            PY[(g * 8 + 7) * PSTR + col] = y67.y;
        }
        cpwaitall();
        __syncthreads();
    }

    // ---- phase 4: O partials (packed i-pairs per g), staged in XS ----
    {
        const int o = t & 255, q = t >> 8, h = o >> 5;
        ull acc2[8];
#pragma unroll
        for (int g = 0; g < 8; ++g) acc2[g] = 0;
        const float* wvp = WKV + 256 + o;
        const int i0 = q * 96;
#pragma unroll 2
        for (int j = 0; j < 24; ++j) {
            int i = i0 + j * 4;
            float w0 = __ldg(&wvp[(size_t)(i + 0) * 512]);
            float w1 = __ldg(&wvp[(size_t)(i + 1) * 512]);
            float w2 = __ldg(&wvp[(size_t)(i + 2) * 512]);
            float w3 = __ldg(&wvp[(size_t)(i + 3) * 512]);
            ull wp01 = pk(w0, w1), wp23 = pk(w2, w3);
#pragma unroll
            for (int g = 0; g < 8; ++g) {
                ulonglong2 y = *(const ulonglong2*)&PY[(g * 8 + h) * PSTR + i];
                fma2(acc2[g], y.x, wp01);
                fma2(acc2[g], y.y, wp23);
            }
        }
        float r[8];
#pragma unroll
        for (int g = 0; g < 8; ++g) r[g] = sum2(acc2[g]);
        float* stg = XS + q * 2048 + o * 8;
        *(float4*)stg       = make_float4(r[0], r[1], r[2], r[3]);
        *(float4*)(stg + 4) = make_float4(r[4], r[5], r[6], r[7]);
    }
    __syncthreads();
    {
        const ull* S = (const ull*)XS;
        ull s = add2(add2(S[t], S[1024 + t]), add2(S[2048 + t], S[3072 + t]));
        ((ull*)Qs)[t] = s;     // OvT in [o][g] layout
    }
    __syncthreads();

    // ---- phase 5: out-proj partials (packed g-pairs), staged in XS1 ----
    {
        const int o = t & 255, q = t >> 8;
        ull a0 = 0, a1 = 0, a2 = 0, a3 = 0;
        const ull* O2 = (const ull*)Qs;
        const int i0 = q * 64;
#pragma unroll 4
        for (int ii = 0; ii < 64; ++ii) {
            int i = i0 + ii;
            ull wp = pack2(__ldg(&WO[i * 256 + o]));
            ulonglong2 va = *(const ulonglong2*)&O2[i * 4];
            ulonglong2 vb = *(const ulonglong2*)&O2[i * 4 + 2];
            fma2(a0, va.x, wp); fma2(a1, va.y, wp);
            fma2(a2, vb.x, wp); fma2(a3, vb.y, wp);
        }
        float2 f0 = unpk(a0), f1 = unpk(a1), f2 = unpk(a2), f3 = unpk(a3);
        float* stg = XS1 + q * 2048 + o * 8;
        *(float4*)stg       = make_float4(f0.x, f0.y, f1.x, f1.y);
        *(float4*)(stg + 4) = make_float4(f2.x, f2.y, f3.x, f3.y);
    }
    __syncthreads();

    // ---- final: residual + LayerNorm ----
    {
        const int o = t & 255, gp = t >> 8;
        float xg[2];
#pragma unroll
        for (int j = 0; j < 2; ++j) {
            int g = gp * 2 + j;
            int idx = o * 8 + g;
            float s = XS1[idx] + XS1[2048 + idx] + XS1[4096 + idx] + XS1[6144 + idx];
            xg[j] = s + __ldg(&bO[o]) + RT[o * 8 + g];
            float s1 = wsum(xg[j]);
            float s2 = wsum(xg[j] * xg[j]);
            if (lane == 0) { red1[wid * 2 + j] = s1; red2[wid * 2 + j] = s2; }
        }
        __syncthreads();
        if (t < 8) {
            int g = t, gq = g >> 1, j = g & 1;
            float t1 = 0.f, t2 = 0.f;
#pragma unroll
            for (int w = 0; w < 8; ++w) {
                t1 += red1[(gq * 8 + w) * 2 + j];
                t2 += red2[(gq * 8 + w) * 2 + j];
            }
            float mu = t1 * (1.0f / 256.0f);
            float var = t2 * (1.0f / 256.0f) - mu * mu;
            muS[g] = mu;
            rsS[g] = rsqrtf(var + 1e-5f);
        }
        __syncthreads();
        float gm = __ldg(&gamma[o]), bt = __ldg(&beta[o]);
#pragma unroll
        for (int j = 0; j < 2; ++j) {
            int g = gp * 2 + j;
            int b = b0 + g;
            if (b < B)
                out[(size_t)b * 256 + o] = (xg[j] - muS[g]) * rsS[g] * gm + bt;
        }
    }
}

extern "C" void kernel_launch(void* const* d_in, const int* in_sizes, int n_in,
                              void* d_out, int out_size) {
    (void)n_in; (void)out_size;
    const float* node  = (const float*)d_in[0];
    const float* timef = (const float*)d_in[1];
    const float* edge  = (const float*)d_in[2];
    const float* nnode = (const float*)d_in[3];
    const float* ntime = (const float*)d_in[4];
    const int*   mask  = (const int*)d_in[5];
    const float* WQ    = (const float*)d_in[6];
    const float* WKV   = (const float*)d_in[7];
    const float* WO    = (const float*)d_in[8];
    const float* bO    = (const float*)d_in[9];
    const float* gamma = (const float*)d_in[10];
    const float* beta  = (const float*)d_in[11];
    float* out = (float*)d_out;

    int B = in_sizes[0] / 128;
    int blocks = (B + G - 1) / G;

    cudaFuncSetAttribute(ta_kernel, cudaFuncAttributeMaxDynamicSharedMemorySize, SMEM_BYTES);
    ta_kernel<<<blocks, NT, SMEM_BYTES>>>(node, timef, edge, nnode, ntime, mask,
                                          WQ, WKV, WO, bO, gamma, beta, out, B);
}

// round 7
// speedup vs baseline: 2.4038x; 1.3572x over previous
#include <cuda_runtime.h>
#include <math.h>

typedef unsigned long long ull;

#define G    8
#define NT   1024
#define XSTR 388
#define PSTR 388

#define RT_OFF   0                        // [256][8]
#define QS_OFF   2048                     // Q as [o][g]; AttP during phase 3; OvT after
#define PY_OFF   4096                     // [8g][8h][388]
#define XS_OFF   (PY_OFF + 24832)         // 2 x [32][388]
#define XS1_OFF  (XS_OFF + 12416)
#define WT2_OFF  (XS_OFF + 24832)         // [4 hp][32 s] float2 = 256 floats
#define RD1_OFF  (WT2_OFF + 256)          // [32][2]
#define RD2_OFF  (RD1_OFF + 64)
#define MU_OFF   (RD2_OFF + 64)
#define RS_OFF   (MU_OFF + 8)
#define CODE_OFF (RS_OFF + 8)             // [8][32] ints
#define LST_OFF  (CODE_OFF + 256)         // [8][32] ints (compacted unmasked indices)
#define MS_OFF   (LST_OFF + 256)          // [8] ints (m per g)
#define SMEM_FLOATS (MS_OFF + 8)
#define SMEM_BYTES  (SMEM_FLOATS * 4)

__device__ __forceinline__ float wsum(float v) {
#pragma unroll
    for (int o = 16; o > 0; o >>= 1) v += __shfl_xor_sync(0xffffffffu, v, o);
    return v;
}
__device__ __forceinline__ float wmax(float v) {
#pragma unroll
    for (int o = 16; o > 0; o >>= 1) v = fmaxf(v, __shfl_xor_sync(0xffffffffu, v, o));
    return v;
}
__device__ __forceinline__ void fma2(ull& d, ull a, ull b) {
    asm("fma.rn.f32x2 %0, %1, %2, %0;" : "+l"(d) : "l"(a), "l"(b));
}
__device__ __forceinline__ ull add2(ull a, ull b) {
    ull r; asm("add.rn.f32x2 %0, %1, %2;" : "=l"(r) : "l"(a), "l"(b)); return r;
}
__device__ __forceinline__ ull pack2(float v) {
    ull r; asm("mov.b64 %0, {%1, %1};" : "=l"(r) : "r"(__float_as_uint(v))); return r;
}
__device__ __forceinline__ ull pk(float a, float b) {
    ull r; asm("mov.b64 %0, {%1, %2};" : "=l"(r) : "r"(__float_as_uint(a)), "r"(__float_as_uint(b))); return r;
}
__device__ __forceinline__ float2 unpk(ull a) {
    float2 f; asm("mov.b64 {%0, %1}, %2;" : "=f"(f.x), "=f"(f.y) : "l"(a)); return f;
}
__device__ __forceinline__ float sum2(ull a) { float2 f = unpk(a); return f.x + f.y; }

__device__ __forceinline__ void cpasync16(void* dst, const void* src) {
    unsigned d = (unsigned)__cvta_generic_to_shared(dst);
    asm volatile("cp.async.cg.shared.global [%0], [%1], 16;\n" :: "r"(d), "l"(src));
}
__device__ __forceinline__ void cpcommit() {
    asm volatile("cp.async.commit_group;\n" ::: "memory");
}
__device__ __forceinline__ void cpwaitall() {
    asm volatile("cp.async.wait_group 0;\n" ::: "memory");
}

// compacted X prefetch: load rows lst[0..m-1], store at compacted slots
__device__ __forceinline__ void prefetchXc(float* Xbuf, long long b,
                                           const int* lst, int m,
                                           const float4* nn4, const float4* ed4, const float4* et4,
                                           int start, int stride) {
    int total = m * 96;
    for (int idx = start; idx < total; idx += stride) {
        int sp = idx / 96, c4 = idx - sp * 96;
        int so = lst[sp];
        long long rb = (b * 32 + so) * 32;
        const float4* src = (c4 < 32) ? nn4 + rb + c4
                          : (c4 < 64) ? ed4 + rb + (c4 - 32)
                                      : et4 + rb + (c4 - 64);
        cpasync16(&Xbuf[sp * XSTR + c4 * 4], src);
    }
}

__global__ __launch_bounds__(NT, 1)
void ta_kernel(const float* __restrict__ node,
               const float* __restrict__ timef,
               const float* __restrict__ edge,
               const float* __restrict__ nnode,
               const float* __restrict__ ntime,
               const int* __restrict__ mask,
               const float* __restrict__ WQ,
               const float* __restrict__ WKV,
               const float* __restrict__ WO,
               const float* __restrict__ bO,
               const float* __restrict__ gamma,
               const float* __restrict__ beta,
               float* __restrict__ out,
               int B)
{
    extern __shared__ float smf[];
    float* RT   = smf + RT_OFF;
    float* Qs   = smf + QS_OFF;      // Q [o][g]; AttP [4][32][8] in phase 3; OvT [o][g] after
    float* PY   = smf + PY_OFF;
    float* XS   = smf + XS_OFF;
    float* XS1  = smf + XS1_OFF;
    float* Wt2  = smf + WT2_OFF;
    float* red1 = smf + RD1_OFF;
    float* red2 = smf + RD2_OFF;
    float* muS  = smf + MU_OFF;
    float* rsS  = smf + RS_OFF;
    int*   codeS = (int*)(smf + CODE_OFF);
    int*   lstS  = (int*)(smf + LST_OFF);
    int*   mS    = (int*)(smf + MS_OFF);

    const int t = threadIdx.x;
    const int wid = t >> 5, lane = t & 31;
    const int b0 = blockIdx.x * G;

    const float4* nn4 = (const float4*)nnode;
    const float4* ed4 = (const float4*)edge;
    const float4* et4 = (const float4*)ntime;

    // ---- phase 0a: masks, compaction lists ----
    if (t < 256) {
        int g = wid;
        int bb = b0 + g; if (bb > B - 1) bb = B - 1;
        int mk = mask[(long long)bb * 32 + lane];
        unsigned bal = __ballot_sync(0xffffffffu, mk != 0);
        int m = __popc(bal);
        if (m == 0) {
            codeS[g * 32 + lane] = 2;
            lstS[g * 32 + lane] = lane;          // identity, m=32 (uniform weights)
            if (lane == 0) mS[g] = 32;
        } else {
            codeS[g * 32 + lane] = mk ? 0 : 1;
            if (mk) lstS[g * 32 + __popc(bal & ((1u << lane) - 1u))] = lane;
            if (lane == 0) mS[g] = m;
        }
    }
    __syncthreads();

    // ---- prefetch X[0] (compacted; overlaps phases 0b-2) ----
    {
        int bb = b0; if (bb > B - 1) bb = B - 1;
        prefetchXc(XS, (long long)bb, &lstS[0], mS[0], nn4, ed4, et4, t, NT);
        cpcommit();
    }

    // ---- phase 0b: RT ----
    for (int idx = t; idx < G * 256; idx += NT) {
        int g = idx & 7, j = idx >> 3;
        int bb = b0 + g; if (bb > B - 1) bb = B - 1;
        long long b = bb;
        float v = (j < 128) ? node[b * 128 + j] : timef[b * 128 + (j - 128)];
        RT[j * G + g] = v;
    }
    __syncthreads();

    // ---- phase 1: Q partials (packed g-pairs), staged in XS1 ----
    {
        const int o = t & 255, q = t >> 8;
        ull a0 = 0, a1 = 0, a2 = 0, a3 = 0;
        const int i0 = q * 64;
        const ull* RT2 = (const ull*)RT;
#pragma unroll 4
        for (int ii = 0; ii < 64; ++ii) {
            int i = i0 + ii;
            ull w2 = pack2(__ldg(&WQ[i * 256 + o]));
            ulonglong2 ra = *(const ulonglong2*)&RT2[i * 4];
            ulonglong2 rb = *(const ulonglong2*)&RT2[i * 4 + 2];
            fma2(a0, ra.x, w2); fma2(a1, ra.y, w2);
            fma2(a2, rb.x, w2); fma2(a3, rb.y, w2);
        }
        ull* stg = (ull*)(XS1 + q * 2048 + o * 8);
        ((ulonglong2*)stg)[0] = make_ulonglong2(a0, a1);
        ((ulonglong2*)stg)[1] = make_ulonglong2(a2, a3);
    }
    __syncthreads();
    {
        const ull* S = (const ull*)XS1;
        ull s = add2(add2(S[t], S[1024 + t]), add2(S[2048 + t], S[3072 + t]));
        ((ull*)Qs)[t] = s;      // Q in [o][g] layout
    }
    __syncthreads();

    // ---- phase 2: P[g][h][i], coalesced WKV loads ----
    // warp = (h = wid>>2, ic = wid&3); lane = (il = lane>>3, q = lane&7)
    {
        const int h = wid >> 2, ic = wid & 3;
        const int il = lane >> 3, q = lane & 7;
        const int q1 = q & 1, q2 = (q >> 1) & 1, q4 = (q >> 2) & 1;

        // Q cache: Qp[e][gp], c = h*32 + q*4 + e
        ull Qp[4][4];
        const ull* Q2 = (const ull*)Qs;
#pragma unroll
        for (int e = 0; e < 4; ++e) {
            int c = h * 32 + q * 4 + e;
            ulonglong2 qa = *(const ulonglong2*)&Q2[c * 4];
            ulonglong2 qb = *(const ulonglong2*)&Q2[c * 4 + 2];
            Qp[e][0] = qa.x; Qp[e][1] = qa.y;
            Qp[e][2] = qb.x; Qp[e][3] = qb.y;
        }

        const int ibase = ic * 96 + il;
#pragma unroll 2
        for (int it = 0; it < 24; ++it) {
            int i = ibase + it * 4;
            float4 wv = __ldg((const float4*)&WKV[(size_t)i * 512 + h * 32 + q * 4]);
            ull acc[4] = {0, 0, 0, 0};
#pragma unroll
            for (int e = 0; e < 4; ++e) {
                ull wp = pack2((&wv.x)[e]);
                fma2(acc[0], Qp[e][0], wp);
                fma2(acc[1], Qp[e][1], wp);
                fma2(acc[2], Qp[e][2], wp);
                fma2(acc[3], Qp[e][3], wp);
            }
            float v[8];
#pragma unroll
            for (int p = 0; p < 4; ++p) {
                float2 f = unpk(acc[p]);
                v[2 * p] = f.x; v[2 * p + 1] = f.y;
            }
            // 3-stage keep-split reduction over q; lane q ends with g = q
            float u[4];
#pragma unroll
            for (int j = 0; j < 4; ++j) {
                float a = v[2 * j], b = v[2 * j + 1];
                float mine = q1 ? b : a;
                float send = q1 ? a : b;
                u[j] = mine + __shfl_xor_sync(0xffffffffu, send, 1);
            }
            float w2_[2];
#pragma unroll
            for (int k = 0; k < 2; ++k) {
                float a = u[2 * k], b = u[2 * k + 1];
                float mine = q2 ? b : a;
                float send = q2 ? a : b;
                w2_[k] = mine + __shfl_xor_sync(0xffffffffu, send, 2);
            }
            {
                float a = w2_[0], b = w2_[1];
                float mine = q4 ? b : a;
                float send = q4 ? a : b;
                float r = mine + __shfl_xor_sync(0xffffffffu, send, 4);
                PY[(q * 8 + h) * PSTR + i] = r;    // g = q
            }
        }
    }
    cpwaitall();
    __syncthreads();

    // ---- phase 3: per-g attention ----
    float* AttP = Qs;    // [4 iq][32 s][8 h] partials (Q is dead now)
#pragma unroll 1
    for (int g = 0; g < G; ++g) {
        float* Xbuf = XS + (g & 1) * 12416;
        const int m = mS[g];

        if (g < G - 1) {
            int bb = b0 + g + 1; if (bb > B - 1) bb = B - 1;
            prefetchXc(XS + ((g + 1) & 1) * 12416, (long long)bb,
                       &lstS[(g + 1) * 32], mS[g + 1], nn4, ed4, et4, t, NT);
        }
        cpcommit();

        // scores: warp = (s-quad, i-quarter); lane = (h, s-local); compacted rows
        {
            const int sq = wid >> 2, iq = wid & 3;
            const int h = lane >> 2, sl = lane & 3;
            if (sq * 4 < m) {
                int sp = sq * 4 + sl;
                bool valid = sp < m;
                int spc = valid ? sp : (m - 1);
                const ulonglong2* X2 = (const ulonglong2*)&Xbuf[spc * XSTR + iq * 96];
                const ulonglong2* P2 = (const ulonglong2*)&PY[(g * 8 + h) * PSTR + iq * 96];
                ull a0 = 0, a1 = 0;
#pragma unroll
                for (int j = 0; j < 24; j += 2) {
                    ulonglong2 x0 = X2[j];
                    ulonglong2 p0 = P2[j];
                    ulonglong2 x1 = X2[j + 1];
                    ulonglong2 p1 = P2[j + 1];
                    fma2(a0, x0.x, p0.x); fma2(a0, x0.y, p0.y);
                    fma2(a1, x1.x, p1.x); fma2(a1, x1.y, p1.y);
                }
                if (valid) {
                    int so = lstS[g * 32 + sp];
                    AttP[iq * 256 + so * 8 + h] = sum2(add2(a0, a1));
                }
            }
        }
        __syncthreads();

        // softmax: warp h (wid<8), lane = s (original index)
        if (wid < 8) {
            const int s = lane;
            int cde = codeS[g * 32 + s];
            float a = AttP[s * 8 + wid] + AttP[256 + s * 8 + wid]
                    + AttP[512 + s * 8 + wid] + AttP[768 + s * 8 + wid];
            float v = (cde == 0) ? a * 0.17677669529663687f
                                 : ((cde == 1) ? -1e10f : 0.f);
            float mx = wmax(v);
            float e = __expf(v - mx);
            float ss = wsum(e);
            Wt2[((wid >> 1) * 32 + s) * 2 + (wid & 1)] = e / ss;
        }
        __syncthreads();

        // Y[g][*][col]: thread = col (384 threads), all 8 heads packed; m iters
        if (t < 384) {
            const int col = t;
            const ull* W2 = (const ull*)Wt2;
            ull acc0 = 0, acc1 = 0, acc2 = 0, acc3 = 0;
#pragma unroll 2
            for (int sp = 0; sp < m; ++sp) {
                int so = lstS[g * 32 + sp];
                ull x2 = pack2(Xbuf[sp * XSTR + col]);
                fma2(acc0, x2, W2[0 * 32 + so]);
                fma2(acc1, x2, W2[1 * 32 + so]);
                fma2(acc2, x2, W2[2 * 32 + so]);
                fma2(acc3, x2, W2[3 * 32 + so]);
            }
            float2 y01 = unpk(acc0), y23 = unpk(acc1);
            float2 y45 = unpk(acc2), y67 = unpk(acc3);
            PY[(g * 8 + 0) * PSTR + col] = y01.x;
            PY[(g * 8 + 1) * PSTR + col] = y01.y;
            PY[(g * 8 + 2) * PSTR + col] = y23.x;
            PY[(g * 8 + 3) * PSTR + col] = y23.y;
            PY[(g * 8 + 4) * PSTR + col] = y45.x;
            PY[(g * 8 + 5) * PSTR + col] = y45.y;
            PY[(g * 8 + 6) * PSTR + col] = y67.x;
            PY[(g * 8 + 7) * PSTR + col] = y67.y;
        }
        cpwaitall();
        __syncthreads();
    }

    // ---- phase 4: O partials (packed i-pairs per g), staged in XS ----
    {
        const int o = t & 255, q = t >> 8, h = o >> 5;
        ull acc2[8];
#pragma unroll
        for (int g = 0; g < 8; ++g) acc2[g] = 0;
        const float* wvp = WKV + 256 + o;
        const int i0 = q * 96;
#pragma unroll 2
        for (int j = 0; j < 24; ++j) {
            int i = i0 + j * 4;
            float w0 = __ldg(&wvp[(size_t)(i + 0) * 512]);
            float w1 = __ldg(&wvp[(size_t)(i + 1) * 512]);
            float w2 = __ldg(&wvp[(size_t)(i + 2) * 512]);
            float w3 = __ldg(&wvp[(size_t)(i + 3) * 512]);
            ull wp01 = pk(w0, w1), wp23 = pk(w2, w3);
#pragma unroll
            for (int g = 0; g < 8; ++g) {
                ulonglong2 y = *(const ulonglong2*)&PY[(g * 8 + h) * PSTR + i];
                fma2(acc2[g], y.x, wp01);
                fma2(acc2[g], y.y, wp23);
            }
        }
        float r[8];
#pragma unroll
        for (int g = 0; g < 8; ++g) r[g] = sum2(acc2[g]);
        float* stg = XS + q * 2048 + o * 8;
        *(float4*)stg       = make_float4(r[0], r[1], r[2], r[3]);
        *(float4*)(stg + 4) = make_float4(r[4], r[5], r[6], r[7]);
    }
    __syncthreads();
    {
        const ull* S = (const ull*)XS;
        ull s = add2(add2(S[t], S[1024 + t]), add2(S[2048 + t], S[3072 + t]));
        ((ull*)Qs)[t] = s;     // OvT in [o][g] layout
    }
    __syncthreads();

    // ---- phase 5: out-proj partials (packed g-pairs), staged in XS1 ----
    {
        const int o = t & 255, q = t >> 8;
        ull a0 = 0, a1 = 0, a2 = 0, a3 = 0;
        const ull* O2 = (const ull*)Qs;
        const int i0 = q * 64;
#pragma unroll 4
        for (int ii = 0; ii < 64; ++ii) {
            int i = i0 + ii;
            ull wp = pack2(__ldg(&WO[i * 256 + o]));
            ulonglong2 va = *(const ulonglong2*)&O2[i * 4];
            ulonglong2 vb = *(const ulonglong2*)&O2[i * 4 + 2];
            fma2(a0, va.x, wp); fma2(a1, va.y, wp);
            fma2(a2, vb.x, wp); fma2(a3, vb.y, wp);
        }
        float2 f0 = unpk(a0), f1 = unpk(a1), f2 = unpk(a2), f3 = unpk(a3);
        float* stg = XS1 + q * 2048 + o * 8;
        *(float4*)stg       = make_float4(f0.x, f0.y, f1.x, f1.y);
        *(float4*)(stg + 4) = make_float4(f2.x, f2.y, f3.x, f3.y);
    }
    __syncthreads();

    // ---- final: residual + LayerNorm ----
    {
        const int o = t & 255, gp = t >> 8;
        float xg[2];
#pragma unroll
        for (int j = 0; j < 2; ++j) {
            int g = gp * 2 + j;
            int idx = o * 8 + g;
            float s = XS1[idx] + XS1[2048 + idx] + XS1[4096 + idx] + XS1[6144 + idx];
            xg[j] = s + __ldg(&bO[o]) + RT[o * 8 + g];
            float s1 = wsum(xg[j]);
            float s2 = wsum(xg[j] * xg[j]);
            if (lane == 0) { red1[wid * 2 + j] = s1; red2[wid * 2 + j] = s2; }
        }
        __syncthreads();
        if (t < 8) {
            int g = t, gq = g >> 1, j = g & 1;
            float t1 = 0.f, t2 = 0.f;
#pragma unroll
            for (int w = 0; w < 8; ++w) {
                t1 += red1[(gq * 8 + w) * 2 + j];
                t2 += red2[(gq * 8 + w) * 2 + j];
            }
            float mu = t1 * (1.0f / 256.0f);
            float var = t2 * (1.0f / 256.0f) - mu * mu;
            muS[g] = mu;
            rsS[g] = rsqrtf(var + 1e-5f);
        }
        __syncthreads();
        float gm = __ldg(&gamma[o]), bt = __ldg(&beta[o]);
#pragma unroll
        for (int j = 0; j < 2; ++j) {
            int g = gp * 2 + j;
            int b = b0 + g;
            if (b < B)
                out[(size_t)b * 256 + o] = (xg[j] - muS[g]) * rsS[g] * gm + bt;
        }
    }
}

extern "C" void kernel_launch(void* const* d_in, const int* in_sizes, int n_in,
                              void* d_out, int out_size) {
    (void)n_in; (void)out_size;
    const float* node  = (const float*)d_in[0];
    const float* timef = (const float*)d_in[1];
    const float* edge  = (const float*)d_in[2];
    const float* nnode = (const float*)d_in[3];
    const float* ntime = (const float*)d_in[4];
    const int*   mask  = (const int*)d_in[5];
    const float* WQ    = (const float*)d_in[6];
    const float* WKV   = (const float*)d_in[7];
    const float* WO    = (const float*)d_in[8];
    const float* bO    = (const float*)d_in[9];
    const float* gamma = (const float*)d_in[10];
    const float* beta  = (const float*)d_in[11];
    float* out = (float*)d_out;

    int B = in_sizes[0] / 128;
    int blocks = (B + G - 1) / G;

    cudaFuncSetAttribute(ta_kernel, cudaFuncAttributeMaxDynamicSharedMemorySize, SMEM_BYTES);
    ta_kernel<<<blocks, NT, SMEM_BYTES>>>(node, timef, edge, nnode, ntime, mask,
                                          WQ, WKV, WO, bO, gamma, beta, out, B);
}